// round 1
// baseline (speedup 1.0000x reference)
#include <cuda_runtime.h>
#include <math.h>

#define BATCH  4
#define SEQ    2048
#define DMODEL 1024
#define NHEADS 16
#define HD     64
#define NF     256
#define BH     (BATCH*NHEADS)       // 128
#define MROWS  (BATCH*SEQ)          // 8192

// ---------------- scratch (static device globals; no allocations) ------------
__device__ float g_q  [MROWS*DMODEL];   // [B,S,D]
__device__ float g_k  [MROWS*DMODEL];
__device__ float g_v  [MROWS*DMODEL];
__device__ float g_ctx[MROWS*DMODEL];
__device__ float g_qp [BH*NF*SEQ];      // [BH, NF, S]  (transposed for attn loads)
__device__ float g_kp [BH*NF*SEQ];

// ---------------- generic C[M,N] = A[M,K] @ W[N,K]^T + b ---------------------
// BM=BN=64, BK=16, 256 threads, 4x4 per thread.
__global__ __launch_bounds__(256) void gemm_xwt(
    const float* __restrict__ A, const float* __restrict__ W,
    const float* __restrict__ bias, float* __restrict__ C,
    int N, int K)
{
    __shared__ float As[16][68];   // [k][row]
    __shared__ float Bs[16][68];   // [k][col]
    const int tid = threadIdx.x;
    const int ty = tid >> 4, tx = tid & 15;
    const int row0 = blockIdx.y * 64;
    const int col0 = blockIdx.x * 64;
    const int lr = tid >> 2;            // 0..63
    const int lk = (tid & 3) << 2;      // 0,4,8,12

    const float* Aptr = A + (row0 + lr) * K + lk;
    const float* Wptr = W + (col0 + lr) * K + lk;

    float c[4][4] = {};
    for (int k0 = 0; k0 < K; k0 += 16) {
        float4 av = *(const float4*)(Aptr + k0);
        float4 wv = *(const float4*)(Wptr + k0);
        As[lk+0][lr] = av.x; As[lk+1][lr] = av.y; As[lk+2][lr] = av.z; As[lk+3][lr] = av.w;
        Bs[lk+0][lr] = wv.x; Bs[lk+1][lr] = wv.y; Bs[lk+2][lr] = wv.z; Bs[lk+3][lr] = wv.w;
        __syncthreads();
        #pragma unroll
        for (int kk = 0; kk < 16; kk++) {
            float4 a4 = *(const float4*)&As[kk][ty << 2];
            float4 b4 = *(const float4*)&Bs[kk][tx << 2];
            float a_[4] = {a4.x, a4.y, a4.z, a4.w};
            float b_[4] = {b4.x, b4.y, b4.z, b4.w};
            #pragma unroll
            for (int i = 0; i < 4; i++)
                #pragma unroll
                for (int j = 0; j < 4; j++)
                    c[i][j] += a_[i] * b_[j];
        }
        __syncthreads();
    }
    float4 bv = *(const float4*)&bias[col0 + (tx << 2)];
    float bb[4] = {bv.x, bv.y, bv.z, bv.w};
    #pragma unroll
    for (int i = 0; i < 4; i++) {
        float4 o4 = make_float4(c[i][0]+bb[0], c[i][1]+bb[1], c[i][2]+bb[2], c[i][3]+bb[3]);
        *(float4*)&C[(row0 + (ty<<2) + i) * N + col0 + (tx<<2)] = o4;
    }
}

// ---------------- feature projection: Out[bh,f,s] = sum_d In[b,s,h*64+d]*P[f,d]
// ty -> f group, tx -> s group (coalesced transposed store)
__global__ __launch_bounds__(256) void featproj(
    const float* __restrict__ In,   // [B,S,D]
    const float* __restrict__ P,    // [NF,HD]
    float* __restrict__ Out)        // [BH,NF,SEQ]
{
    __shared__ float Qsm[16][68];   // [d][s]
    __shared__ float Psm[16][68];   // [d][f]
    const int bh = blockIdx.z, b = bh >> 4, h = bh & 15;
    const int s0 = blockIdx.x * 64, f0 = blockIdx.y * 64;
    const int tid = threadIdx.x;
    const int ty = tid >> 4, tx = tid & 15;
    const int lr = tid >> 2;
    const int lk = (tid & 3) << 2;

    const float* qptr = In + ((b * SEQ) + s0 + lr) * DMODEL + h * HD + lk;
    const float* pptr = P + (f0 + lr) * HD + lk;

    float c[4][4] = {};   // [f i][s j]
    for (int k0 = 0; k0 < HD; k0 += 16) {
        float4 qv = *(const float4*)(qptr + k0);
        float4 pv = *(const float4*)(pptr + k0);
        Qsm[lk+0][lr] = qv.x; Qsm[lk+1][lr] = qv.y; Qsm[lk+2][lr] = qv.z; Qsm[lk+3][lr] = qv.w;
        Psm[lk+0][lr] = pv.x; Psm[lk+1][lr] = pv.y; Psm[lk+2][lr] = pv.z; Psm[lk+3][lr] = pv.w;
        __syncthreads();
        #pragma unroll
        for (int kk = 0; kk < 16; kk++) {
            float4 a4 = *(const float4*)&Psm[kk][ty << 2];
            float4 b4 = *(const float4*)&Qsm[kk][tx << 2];
            float a_[4] = {a4.x, a4.y, a4.z, a4.w};
            float b_[4] = {b4.x, b4.y, b4.z, b4.w};
            #pragma unroll
            for (int i = 0; i < 4; i++)
                #pragma unroll
                for (int j = 0; j < 4; j++)
                    c[i][j] += a_[i] * b_[j];
        }
        __syncthreads();
    }
    #pragma unroll
    for (int i = 0; i < 4; i++) {
        float4 o4 = make_float4(c[i][0], c[i][1], c[i][2], c[i][3]);
        *(float4*)&Out[(bh * NF + f0 + (ty<<2) + i) * SEQ + s0 + (tx<<2)] = o4;
    }
}

// ---------------- flash attention, fp32, d_eff = NF = 256, hd = 64 -----------
// grid: (SEQ/64, BH). 256 threads. Q tile (64x256) resident in smem.
__global__ __launch_bounds__(256) void attn_kernel(
    const float* __restrict__ QP,   // [BH,NF,SEQ]
    const float* __restrict__ KP,   // [BH,NF,SEQ]
    const float* __restrict__ V,    // [B,S,D]
    float* __restrict__ Ctx)        // [B,S,D]
{
    extern __shared__ float sm[];
    float* Qs = sm;                   // [NF][64]  (f-major)
    float* Ks = sm + NF * 64;         // [64 f][64 t]
    float* Vs = Ks + 64 * 64;         // [64 t][64 d]
    float* Ps = Vs + 64 * 64;         // [64 q][64 t]

    const int tid = threadIdx.x;
    const int ty = tid >> 4, tx = tid & 15;   // ty: q rows, tx: t cols / d cols
    const int bh = blockIdx.y, b = bh >> 4, h = bh & 15;
    const int s0 = blockIdx.x * 64;
    const float scale = 0.0625f;   // 1/sqrt(256)

    // load Q tile (once)
    for (int idx = tid; idx < NF * 16; idx += 256) {
        int f = idx >> 4, qq = (idx & 15) << 2;
        *(float4*)&Qs[f * 64 + qq] = *(const float4*)&QP[(bh * NF + f) * SEQ + s0 + qq];
    }

    float o[4][4] = {};
    float m_[4], l_[4];
    #pragma unroll
    for (int i = 0; i < 4; i++) { m_[i] = -1e30f; l_[i] = 0.f; }

    for (int t0 = 0; t0 < SEQ; t0 += 64) {
        float c[4][4] = {};
        #pragma unroll 1
        for (int fc = 0; fc < 4; fc++) {
            __syncthreads();
            for (int idx = tid; idx < 64 * 16; idx += 256) {
                int ff = idx >> 4, tt = (idx & 15) << 2;
                *(float4*)&Ks[ff * 64 + tt] =
                    *(const float4*)&KP[(bh * NF + fc * 64 + ff) * SEQ + t0 + tt];
            }
            if (fc == 0) {
                for (int idx = tid; idx < 64 * 16; idx += 256) {
                    int t = idx >> 4, dd = (idx & 15) << 2;
                    *(float4*)&Vs[t * 64 + dd] =
                        *(const float4*)&V[(b * SEQ + t0 + t) * DMODEL + h * HD + dd];
                }
            }
            __syncthreads();
            #pragma unroll 8
            for (int ff = 0; ff < 64; ff++) {
                float4 a4 = *(const float4*)&Qs[(fc * 64 + ff) * 64 + (ty << 2)];
                float4 b4 = *(const float4*)&Ks[ff * 64 + (tx << 2)];
                float a_[4] = {a4.x, a4.y, a4.z, a4.w};
                float b_[4] = {b4.x, b4.y, b4.z, b4.w};
                #pragma unroll
                for (int i = 0; i < 4; i++)
                    #pragma unroll
                    for (int j = 0; j < 4; j++)
                        c[i][j] += a_[i] * b_[j];
            }
        }
        // online softmax
        #pragma unroll
        for (int i = 0; i < 4; i++) {
            float r = -1e30f;
            #pragma unroll
            for (int j = 0; j < 4; j++) { c[i][j] *= scale; r = fmaxf(r, c[i][j]); }
            #pragma unroll
            for (int off = 8; off > 0; off >>= 1)
                r = fmaxf(r, __shfl_xor_sync(0xffffffffu, r, off));
            float mn = fmaxf(m_[i], r);
            float alpha = __expf(m_[i] - mn);
            float p[4], rs = 0.f;
            #pragma unroll
            for (int j = 0; j < 4; j++) { p[j] = __expf(c[i][j] - mn); rs += p[j]; }
            *(float4*)&Ps[((ty << 2) + i) * 64 + (tx << 2)] = make_float4(p[0], p[1], p[2], p[3]);
            #pragma unroll
            for (int off = 8; off > 0; off >>= 1)
                rs += __shfl_xor_sync(0xffffffffu, rs, off);
            l_[i] = l_[i] * alpha + rs;
            m_[i] = mn;
            #pragma unroll
            for (int j = 0; j < 4; j++) o[i][j] *= alpha;
        }
        __syncthreads();
        // O += P @ V
        #pragma unroll 4
        for (int t = 0; t < 64; t++) {
            float4 b4 = *(const float4*)&Vs[t * 64 + (tx << 2)];
            float bb[4] = {b4.x, b4.y, b4.z, b4.w};
            #pragma unroll
            for (int i = 0; i < 4; i++) {
                float a = Ps[((ty << 2) + i) * 64 + t];
                #pragma unroll
                for (int j = 0; j < 4; j++) o[i][j] += a * bb[j];
            }
        }
    }
    #pragma unroll
    for (int i = 0; i < 4; i++) {
        float inv = 1.0f / l_[i];
        float4 o4 = make_float4(o[i][0]*inv, o[i][1]*inv, o[i][2]*inv, o[i][3]*inv);
        *(float4*)&Ctx[(b * SEQ + s0 + (ty<<2) + i) * DMODEL + h * HD + (tx<<2)] = o4;
    }
}

// ---------------- launch ------------------------------------------------------
extern "C" void kernel_launch(void* const* d_in, const int* in_sizes, int n_in,
                              void* d_out, int out_size)
{
    (void)in_sizes; (void)n_in; (void)out_size;
    const float* x  = (const float*)d_in[0];
    const float* Wq = (const float*)d_in[1];
    const float* bq = (const float*)d_in[2];
    const float* Wk = (const float*)d_in[3];
    const float* bk = (const float*)d_in[4];
    const float* Wv = (const float*)d_in[5];
    const float* bv = (const float*)d_in[6];
    const float* Wo = (const float*)d_in[7];
    const float* bo = (const float*)d_in[8];
    const float* P  = (const float*)d_in[9];

    float *q, *k, *v, *ctx, *qp, *kp;
    cudaGetSymbolAddress((void**)&q,   g_q);
    cudaGetSymbolAddress((void**)&k,   g_k);
    cudaGetSymbolAddress((void**)&v,   g_v);
    cudaGetSymbolAddress((void**)&ctx, g_ctx);
    cudaGetSymbolAddress((void**)&qp,  g_qp);
    cudaGetSymbolAddress((void**)&kp,  g_kp);

    dim3 gemm_grid(DMODEL / 64, MROWS / 64);   // (16, 128)
    gemm_xwt<<<gemm_grid, 256>>>(x, Wq, bq, q, DMODEL, DMODEL);
    gemm_xwt<<<gemm_grid, 256>>>(x, Wk, bk, k, DMODEL, DMODEL);
    gemm_xwt<<<gemm_grid, 256>>>(x, Wv, bv, v, DMODEL, DMODEL);

    dim3 fp_grid(SEQ / 64, NF / 64, BH);       // (32, 4, 128)
    featproj<<<fp_grid, 256>>>(q, P, qp);
    featproj<<<fp_grid, 256>>>(k, P, kp);

    const int ATT_SMEM = (NF * 64 + 3 * 64 * 64) * 4;   // 114688 bytes
    cudaFuncSetAttribute(attn_kernel, cudaFuncAttributeMaxDynamicSharedMemorySize, ATT_SMEM);
    attn_kernel<<<dim3(SEQ / 64, BH), 256, ATT_SMEM>>>(qp, kp, v, ctx);

    gemm_xwt<<<gemm_grid, 256>>>(ctx, Wo, bo, (float*)d_out, DMODEL, DMODEL);
}

// round 4
// speedup vs baseline: 1.1288x; 1.1288x over previous
#include <cuda_runtime.h>
#include <math.h>
#include <stdint.h>

#define BATCH  4
#define SEQ    2048
#define DMODEL 1024
#define NHEADS 16
#define HD     64
#define NF     256
#define BH     (BATCH*NHEADS)       // 128
#define MROWS  (BATCH*SEQ)          // 8192

// ---------------- scratch (static device globals; no allocations) ------------
__device__ float g_q  [MROWS*DMODEL];   // [B,S,D]
__device__ float g_k  [MROWS*DMODEL];
__device__ float g_v  [MROWS*DMODEL];
__device__ float g_ctx[MROWS*DMODEL];
__device__ float g_qp [BH*SEQ*NF];      // [BH, S, NF]
__device__ float g_kp [BH*SEQ*NF];

// ---------------- helpers ----------------------------------------------------
// split x into tf32 hi + tf32 lo (error ~2^-22 |x|)
__device__ __forceinline__ void split_tf(float x, uint32_t& hi, uint32_t& lo) {
    uint32_t hb;
    asm("cvt.rna.tf32.f32 %0, %1;" : "=r"(hb) : "f"(x));
    hi = hb;
    float r = x - __uint_as_float(hb);
    asm("cvt.rna.tf32.f32 %0, %1;" : "=r"(lo) : "f"(r));
}

// D += A*B, m16n8k8 tf32. A row-major frag (4 regs), B col-major frag (2 regs).
__device__ __forceinline__ void mma8(float* c, const uint32_t* a, const uint32_t* b) {
    asm volatile(
        "mma.sync.aligned.m16n8k8.row.col.f32.tf32.tf32.f32 "
        "{%0,%1,%2,%3}, {%4,%5,%6,%7}, {%8,%9}, {%0,%1,%2,%3};\n"
        : "+f"(c[0]), "+f"(c[1]), "+f"(c[2]), "+f"(c[3])
        : "r"(a[0]), "r"(a[1]), "r"(a[2]), "r"(a[3]), "r"(b[0]), "r"(b[1]));
}

// 3xTF32: c += Ahi*Bhi + Ahi*Blo + Alo*Bhi
__device__ __forceinline__ void mma3(float* c, const uint32_t* ah, const uint32_t* al,
                                     const uint32_t* bh, const uint32_t* bl) {
    mma8(c, ah, bl);
    mma8(c, al, bh);
    mma8(c, ah, bh);
}

// ---------------- 3xTF32 GEMM: C[M,N] = A[M,K] @ W[N,K]^T + b ----------------
// Block tile 128x64, 8 warps of 32x32, BK=32. Pitch 36 => conflict-free frags.
__global__ __launch_bounds__(256) void gemm_mma(
    const float* __restrict__ A, const float* __restrict__ W,
    const float* __restrict__ bias, float* __restrict__ C,
    int N, int K)
{
    __shared__ float As[128 * 36];
    __shared__ float Ws[64 * 36];
    const int tid  = threadIdx.x;
    const int lane = tid & 31, warp = tid >> 5;
    const int g = lane >> 2, tig = lane & 3;
    const int wq = warp >> 1, wn = warp & 1;
    const int row0 = blockIdx.y * 128, col0 = blockIdx.x * 64;

    const int ar = tid >> 1, ak = (tid & 1) * 16;   // A loader: 128 rows x 32k
    const int wr = tid >> 2, wk = (tid & 3) * 8;    // W loader: 64 rows x 32k

    float c[2][4][4] = {};

    for (int k0 = 0; k0 < K; k0 += 32) {
        __syncthreads();
        {
            const float* src = A + (size_t)(row0 + ar) * K + k0 + ak;
            float* d = As + ar * 36 + ak;
            *(float4*)(d    ) = *(const float4*)(src    );
            *(float4*)(d + 4) = *(const float4*)(src + 4);
            *(float4*)(d + 8) = *(const float4*)(src + 8);
            *(float4*)(d +12) = *(const float4*)(src +12);
        }
        {
            const float* src = W + (size_t)(col0 + wr) * K + k0 + wk;
            float* d = Ws + wr * 36 + wk;
            *(float4*)(d    ) = *(const float4*)(src    );
            *(float4*)(d + 4) = *(const float4*)(src + 4);
        }
        __syncthreads();
        #pragma unroll
        for (int k8 = 0; k8 < 4; k8++) {
            uint32_t ah[2][4], al[2][4], bh[4][2], bl[4][2];
            #pragma unroll
            for (int mi = 0; mi < 2; mi++) {
                int r = wq * 32 + mi * 16;
                split_tf(As[(r + g    ) * 36 + k8 * 8 + tig    ], ah[mi][0], al[mi][0]);
                split_tf(As[(r + g + 8) * 36 + k8 * 8 + tig    ], ah[mi][1], al[mi][1]);
                split_tf(As[(r + g    ) * 36 + k8 * 8 + tig + 4], ah[mi][2], al[mi][2]);
                split_tf(As[(r + g + 8) * 36 + k8 * 8 + tig + 4], ah[mi][3], al[mi][3]);
            }
            #pragma unroll
            for (int n = 0; n < 4; n++) {
                int cc = wn * 32 + n * 8 + g;
                split_tf(Ws[cc * 36 + k8 * 8 + tig    ], bh[n][0], bl[n][0]);
                split_tf(Ws[cc * 36 + k8 * 8 + tig + 4], bh[n][1], bl[n][1]);
            }
            #pragma unroll
            for (int mi = 0; mi < 2; mi++)
                #pragma unroll
                for (int n = 0; n < 4; n++)
                    mma3(c[mi][n], ah[mi], al[mi], bh[n], bl[n]);
        }
    }
    #pragma unroll
    for (int mi = 0; mi < 2; mi++) {
        #pragma unroll
        for (int n = 0; n < 4; n++) {
            int col = col0 + wn * 32 + n * 8 + 2 * tig;
            float b0 = bias[col], b1 = bias[col + 1];
            int r0 = row0 + wq * 32 + mi * 16 + g;
            *(float2*)&C[(size_t)r0 * N + col] =
                make_float2(c[mi][n][0] + b0, c[mi][n][1] + b1);
            *(float2*)&C[(size_t)(r0 + 8) * N + col] =
                make_float2(c[mi][n][2] + b0, c[mi][n][3] + b1);
        }
    }
}

// ---------------- feature projection: Out[bh,s,f] = sum_d In[b,s,h*64+d]*P[f,d]
// fp32 FFMA (exact); output layout [BH,S,NF]
__global__ __launch_bounds__(256) void featproj(
    const float* __restrict__ In,   // [B,S,D]
    const float* __restrict__ P,    // [NF,HD]
    float* __restrict__ Out)        // [BH,SEQ,NF]
{
    __shared__ float Qsm[16][68];   // [d][s]
    __shared__ float Psm[16][68];   // [d][f]
    const int bh = blockIdx.z, b = bh >> 4, h = bh & 15;
    const int s0 = blockIdx.x * 64, f0 = blockIdx.y * 64;
    const int tid = threadIdx.x;
    const int ty = tid >> 4, tx = tid & 15;
    const int lr = tid >> 2;
    const int lk = (tid & 3) << 2;

    const float* qptr = In + ((size_t)(b * SEQ) + s0 + lr) * DMODEL + h * HD + lk;
    const float* pptr = P + (f0 + lr) * HD + lk;

    float c[4][4] = {};   // [s i][f j]
    for (int k0 = 0; k0 < HD; k0 += 16) {
        float4 qv = *(const float4*)(qptr + k0);
        float4 pv = *(const float4*)(pptr + k0);
        Qsm[lk+0][lr] = qv.x; Qsm[lk+1][lr] = qv.y; Qsm[lk+2][lr] = qv.z; Qsm[lk+3][lr] = qv.w;
        Psm[lk+0][lr] = pv.x; Psm[lk+1][lr] = pv.y; Psm[lk+2][lr] = pv.z; Psm[lk+3][lr] = pv.w;
        __syncthreads();
        #pragma unroll
        for (int kk = 0; kk < 16; kk++) {
            float4 a4 = *(const float4*)&Qsm[kk][ty << 2];
            float4 b4 = *(const float4*)&Psm[kk][tx << 2];
            float a_[4] = {a4.x, a4.y, a4.z, a4.w};
            float b_[4] = {b4.x, b4.y, b4.z, b4.w};
            #pragma unroll
            for (int i = 0; i < 4; i++)
                #pragma unroll
                for (int j = 0; j < 4; j++)
                    c[i][j] += a_[i] * b_[j];
        }
        __syncthreads();
    }
    #pragma unroll
    for (int i = 0; i < 4; i++) {
        float4 o4 = make_float4(c[i][0], c[i][1], c[i][2], c[i][3]);
        *(float4*)&Out[((size_t)bh * SEQ + s0 + (ty << 2) + i) * NF + f0 + (tx << 2)] = o4;
    }
}

// ---------------- flash attention, 3xTF32 MMA, d_eff = NF = 256 --------------
// Block: 128 q x 64 t, 8 warps (4 q-groups x 2 t/d-halves), K streamed in
// 64-feature chunks. ~200KB dynamic smem, 1 CTA/SM.
#define QT 128
#define TT 64
#define QPITCH 260
#define KPITCH 68
#define VPITCH 72
#define PPITCH 68

__global__ __launch_bounds__(256) void attn_mma(
    const float* __restrict__ QP,   // [BH,S,NF]
    const float* __restrict__ KP,   // [BH,S,NF]
    const float* __restrict__ V,    // [B,S,D]
    float* __restrict__ Ctx)        // [B,S,D]
{
    extern __shared__ float sm[];
    float* Qs = sm;                          // 128*260
    float* Ks = Qs + QT * QPITCH;            // 64*68
    float* Vs = Ks + TT * KPITCH;            // 64*72
    float* Ps = Vs + TT * VPITCH;            // 128*68
    float* alpha_sm = Ps + QT * PPITCH;      // 128
    float* l_sm = alpha_sm + QT;             // 128

    const int tid  = threadIdx.x;
    const int lane = tid & 31, warp = tid >> 5;
    const int g = lane >> 2, tig = lane & 3;
    const int wq = warp >> 1, wt = warp & 1;
    const int bh = blockIdx.y, b = bh >> 4, h = bh & 15;
    const int s0 = blockIdx.x * QT;
    const float scale = 0.0625f;   // 1/sqrt(256)

    // load Q tile [128 x 256] raw fp32
    for (int idx = tid; idx < QT * (NF / 4); idx += 256) {
        int r = idx >> 6, f4 = (idx & 63) << 2;
        *(float4*)&Qs[r * QPITCH + f4] =
            *(const float4*)&QP[((size_t)bh * SEQ + s0 + r) * NF + f4];
    }

    float o[2][4][4] = {};
    const int srow = tid >> 1;           // softmax: 2 threads per row
    const int scb  = (tid & 1) * 32;
    float m_ = -1e30f, l_ = 0.f;

    for (int t0 = 0; t0 < SEQ; t0 += TT) {
        float c[2][4][4] = {};
        for (int fc = 0; fc < 4; fc++) {
            __syncthreads();
            for (int idx = tid; idx < TT * 16; idx += 256) {
                int t = idx >> 4, ff = (idx & 15) << 2;
                *(float4*)&Ks[t * KPITCH + ff] =
                    *(const float4*)&KP[((size_t)bh * SEQ + t0 + t) * NF + fc * 64 + ff];
            }
            if (fc == 0) {
                for (int idx = tid; idx < TT * 16; idx += 256) {
                    int t = idx >> 4, dd = (idx & 15) << 2;
                    *(float4*)&Vs[t * VPITCH + dd] =
                        *(const float4*)&V[((size_t)b * SEQ + t0 + t) * DMODEL + h * HD + dd];
                }
            }
            __syncthreads();
            #pragma unroll
            for (int k8 = 0; k8 < 8; k8++) {
                int kq = fc * 64 + k8 * 8;
                uint32_t ah[2][4], al[2][4], bh_[4][2], bl_[4][2];
                #pragma unroll
                for (int mi = 0; mi < 2; mi++) {
                    int r = wq * 32 + mi * 16;
                    split_tf(Qs[(r + g    ) * QPITCH + kq + tig    ], ah[mi][0], al[mi][0]);
                    split_tf(Qs[(r + g + 8) * QPITCH + kq + tig    ], ah[mi][1], al[mi][1]);
                    split_tf(Qs[(r + g    ) * QPITCH + kq + tig + 4], ah[mi][2], al[mi][2]);
                    split_tf(Qs[(r + g + 8) * QPITCH + kq + tig + 4], ah[mi][3], al[mi][3]);
                }
                #pragma unroll
                for (int n = 0; n < 4; n++) {
                    int tc = wt * 32 + n * 8 + g;
                    split_tf(Ks[tc * KPITCH + k8 * 8 + tig    ], bh_[n][0], bl_[n][0]);
                    split_tf(Ks[tc * KPITCH + k8 * 8 + tig + 4], bh_[n][1], bl_[n][1]);
                }
                #pragma unroll
                for (int mi = 0; mi < 2; mi++)
                    #pragma unroll
                    for (int n = 0; n < 4; n++)
                        mma3(c[mi][n], ah[mi], al[mi], bh_[n], bl_[n]);
            }
        }
        // scores -> Ps (raw fp32)
        #pragma unroll
        for (int mi = 0; mi < 2; mi++)
            #pragma unroll
            for (int n = 0; n < 4; n++) {
                int r = wq * 32 + mi * 16 + g;
                int cc = wt * 32 + n * 8 + 2 * tig;
                *(float2*)&Ps[r * PPITCH + cc] = make_float2(c[mi][n][0], c[mi][n][1]);
                *(float2*)&Ps[(r + 8) * PPITCH + cc] = make_float2(c[mi][n][2], c[mi][n][3]);
            }
        __syncthreads();
        // online softmax (2 threads per row, 32 cols each)
        {
            float vals[32];
            float4* prow = (float4*)(Ps + srow * PPITCH + scb);
            #pragma unroll
            for (int i = 0; i < 8; i++) {
                float4 v = prow[i];
                vals[i*4+0]=v.x*scale; vals[i*4+1]=v.y*scale;
                vals[i*4+2]=v.z*scale; vals[i*4+3]=v.w*scale;
            }
            float mx = -1e30f;
            #pragma unroll
            for (int i = 0; i < 32; i++) mx = fmaxf(mx, vals[i]);
            mx = fmaxf(mx, __shfl_xor_sync(0xffffffffu, mx, 1));
            float mn = fmaxf(m_, mx);
            float alpha = __expf(m_ - mn);
            float sum = 0.f;
            #pragma unroll
            for (int i = 0; i < 32; i++) { vals[i] = __expf(vals[i] - mn); sum += vals[i]; }
            sum += __shfl_xor_sync(0xffffffffu, sum, 1);
            l_ = l_ * alpha + sum; m_ = mn;
            #pragma unroll
            for (int i = 0; i < 8; i++)
                prow[i] = make_float4(vals[i*4], vals[i*4+1], vals[i*4+2], vals[i*4+3]);
            if ((tid & 1) == 0) alpha_sm[srow] = alpha;
        }
        __syncthreads();
        // rescale O by alpha
        #pragma unroll
        for (int mi = 0; mi < 2; mi++) {
            int r = wq * 32 + mi * 16;
            float a0 = alpha_sm[r + g], a8 = alpha_sm[r + g + 8];
            #pragma unroll
            for (int n = 0; n < 4; n++) {
                o[mi][n][0] *= a0; o[mi][n][1] *= a0;
                o[mi][n][2] *= a8; o[mi][n][3] *= a8;
            }
        }
        // O += P @ V (3xTF32)
        #pragma unroll
        for (int k8 = 0; k8 < 8; k8++) {
            uint32_t ah[2][4], al[2][4], bh_[4][2], bl_[4][2];
            #pragma unroll
            for (int mi = 0; mi < 2; mi++) {
                int r = wq * 32 + mi * 16;
                split_tf(Ps[(r + g    ) * PPITCH + k8 * 8 + tig    ], ah[mi][0], al[mi][0]);
                split_tf(Ps[(r + g + 8) * PPITCH + k8 * 8 + tig    ], ah[mi][1], al[mi][1]);
                split_tf(Ps[(r + g    ) * PPITCH + k8 * 8 + tig + 4], ah[mi][2], al[mi][2]);
                split_tf(Ps[(r + g + 8) * PPITCH + k8 * 8 + tig + 4], ah[mi][3], al[mi][3]);
            }
            #pragma unroll
            for (int n = 0; n < 4; n++) {
                int dc = wt * 32 + n * 8 + g;
                split_tf(Vs[(k8 * 8 + tig    ) * VPITCH + dc], bh_[n][0], bl_[n][0]);
                split_tf(Vs[(k8 * 8 + tig + 4) * VPITCH + dc], bh_[n][1], bl_[n][1]);
            }
            #pragma unroll
            for (int mi = 0; mi < 2; mi++)
                #pragma unroll
                for (int n = 0; n < 4; n++)
                    mma3(o[mi][n], ah[mi], al[mi], bh_[n], bl_[n]);
        }
    }
    if ((tid & 1) == 0) l_sm[srow] = l_;
    __syncthreads();
    #pragma unroll
    for (int mi = 0; mi < 2; mi++)
        #pragma unroll
        for (int n = 0; n < 4; n++) {
            int r = wq * 32 + mi * 16 + g;
            int dc = wt * 32 + n * 8 + 2 * tig;
            float inv0 = 1.0f / l_sm[r], inv8 = 1.0f / l_sm[r + 8];
            *(float2*)&Ctx[((size_t)b * SEQ + s0 + r) * DMODEL + h * HD + dc] =
                make_float2(o[mi][n][0] * inv0, o[mi][n][1] * inv0);
            *(float2*)&Ctx[((size_t)b * SEQ + s0 + r + 8) * DMODEL + h * HD + dc] =
                make_float2(o[mi][n][2] * inv8, o[mi][n][3] * inv8);
        }
}

// ---------------- launch ------------------------------------------------------
extern "C" void kernel_launch(void* const* d_in, const int* in_sizes, int n_in,
                              void* d_out, int out_size)
{
    (void)in_sizes; (void)n_in; (void)out_size;
    const float* x  = (const float*)d_in[0];
    const float* Wq = (const float*)d_in[1];
    const float* bq = (const float*)d_in[2];
    const float* Wk = (const float*)d_in[3];
    const float* bk = (const float*)d_in[4];
    const float* Wv = (const float*)d_in[5];
    const float* bv = (const float*)d_in[6];
    const float* Wo = (const float*)d_in[7];
    const float* bo = (const float*)d_in[8];
    const float* P  = (const float*)d_in[9];

    float *q, *k, *v, *ctx, *qp, *kp;
    cudaGetSymbolAddress((void**)&q,   g_q);
    cudaGetSymbolAddress((void**)&k,   g_k);
    cudaGetSymbolAddress((void**)&v,   g_v);
    cudaGetSymbolAddress((void**)&ctx, g_ctx);
    cudaGetSymbolAddress((void**)&qp,  g_qp);
    cudaGetSymbolAddress((void**)&kp,  g_kp);

    dim3 gemm_grid(DMODEL / 64, MROWS / 128);   // (16, 64)
    gemm_mma<<<gemm_grid, 256>>>(x, Wq, bq, q, DMODEL, DMODEL);
    gemm_mma<<<gemm_grid, 256>>>(x, Wk, bk, k, DMODEL, DMODEL);
    gemm_mma<<<gemm_grid, 256>>>(x, Wv, bv, v, DMODEL, DMODEL);

    dim3 fp_grid(SEQ / 64, NF / 64, BH);        // (32, 4, 128)
    featproj<<<fp_grid, 256>>>(q, P, qp);
    featproj<<<fp_grid, 256>>>(k, P, kp);

    const int ATT_SMEM = (QT * QPITCH + TT * KPITCH + TT * VPITCH + QT * PPITCH + 2 * QT) * 4;
    cudaFuncSetAttribute(attn_mma, cudaFuncAttributeMaxDynamicSharedMemorySize, ATT_SMEM);
    attn_mma<<<dim3(SEQ / QT, BH), 256, ATT_SMEM>>>(qp, kp, v, ctx);

    gemm_mma<<<gemm_grid, 256>>>(ctx, Wo, bo, (float*)d_out, DMODEL, DMODEL);
}

// round 5
// speedup vs baseline: 1.4434x; 1.2787x over previous
#include <cuda_runtime.h>
#include <cuda_bf16.h>
#include <math.h>
#include <stdint.h>

#define BATCH  4
#define SEQ    2048
#define DMODEL 1024
#define NHEADS 16
#define HD     64
#define NF     256
#define BH     (BATCH*NHEADS)       // 128
#define MROWS  (BATCH*SEQ)          // 8192

// ---------------- scratch (static device globals; no allocations) ------------
__device__ float g_q  [MROWS*DMODEL];   // [B,S,D]
__device__ float g_k  [MROWS*DMODEL];
__device__ float g_v  [MROWS*DMODEL];
__device__ float g_ctx[MROWS*DMODEL];
// packed bf16x2 hi/lo feature projections, [BH][SEQ][NF/2] words
__device__ uint32_t g_qph[(size_t)BH*SEQ*(NF/2)];
__device__ uint32_t g_qpl[(size_t)BH*SEQ*(NF/2)];
__device__ uint32_t g_kph[(size_t)BH*SEQ*(NF/2)];
__device__ uint32_t g_kpl[(size_t)BH*SEQ*(NF/2)];

// ---------------- helpers ----------------------------------------------------
// split (x,y) into packed bf16x2 hi + lo words (x in low half)
__device__ __forceinline__ void split_pack(float x, float y, uint32_t& hi, uint32_t& lo) {
    __nv_bfloat162 h = __floats2bfloat162_rn(x, y);
    float hx = __bfloat162float(h.x);
    float hy = __bfloat162float(h.y);
    __nv_bfloat162 l = __floats2bfloat162_rn(x - hx, y - hy);
    hi = *reinterpret_cast<uint32_t*>(&h);
    lo = *reinterpret_cast<uint32_t*>(&l);
}

// C += A*B, m16n8k16 bf16, fp32 accum. A row-major (4 regs), B col-major (2 regs).
__device__ __forceinline__ void mma16(float* c, const uint32_t* a, const uint32_t* b) {
    asm volatile(
        "mma.sync.aligned.m16n8k16.row.col.f32.bf16.bf16.f32 "
        "{%0,%1,%2,%3}, {%4,%5,%6,%7}, {%8,%9}, {%0,%1,%2,%3};\n"
        : "+f"(c[0]), "+f"(c[1]), "+f"(c[2]), "+f"(c[3])
        : "r"(a[0]), "r"(a[1]), "r"(a[2]), "r"(a[3]), "r"(b[0]), "r"(b[1]));
}

__device__ __forceinline__ void mma3(float* c, const uint32_t* ah, const uint32_t* al,
                                     const uint32_t* bh, const uint32_t* bl) {
    mma16(c, ah, bl);
    mma16(c, al, bh);
    mma16(c, ah, bh);
}

// ---------------- bf16x3 GEMM: C[M,N] = A[M,K] @ W[N,K]^T + b ----------------
// Block tile 128x64, 8 warps of 32x32, BK=32. Split at smem-fill time.
// Packed word pitch 20 (16 data + 4 pad) => conflict-free fragment loads.
__global__ __launch_bounds__(256) void gemm_bf3(
    const float* __restrict__ A, const float* __restrict__ W,
    const float* __restrict__ bias, float* __restrict__ C,
    int N, int K)
{
    __shared__ uint32_t Ash[128 * 20], Asl[128 * 20];
    __shared__ uint32_t Wsh[64 * 20],  Wsl[64 * 20];
    const int tid  = threadIdx.x;
    const int lane = tid & 31, warp = tid >> 5;
    const int g = lane >> 2, tig = lane & 3;
    const int wq = warp >> 1, wn = warp & 1;
    const int row0 = blockIdx.y * 128, col0 = blockIdx.x * 64;

    const int ar = tid >> 1, ak = (tid & 1) * 16;   // A loader: 128 rows x 32k
    const int wr = tid >> 2, wk = (tid & 3) * 8;    // W loader: 64 rows x 32k

    float c[2][4][4] = {};

    for (int k0 = 0; k0 < K; k0 += 32) {
        __syncthreads();
        {
            const float* src = A + (size_t)(row0 + ar) * K + k0 + ak;
            float4 v0 = *(const float4*)(src);
            float4 v1 = *(const float4*)(src + 4);
            float4 v2 = *(const float4*)(src + 8);
            float4 v3 = *(const float4*)(src + 12);
            int w = ar * 20 + (ak >> 1);
            split_pack(v0.x, v0.y, Ash[w+0], Asl[w+0]);
            split_pack(v0.z, v0.w, Ash[w+1], Asl[w+1]);
            split_pack(v1.x, v1.y, Ash[w+2], Asl[w+2]);
            split_pack(v1.z, v1.w, Ash[w+3], Asl[w+3]);
            split_pack(v2.x, v2.y, Ash[w+4], Asl[w+4]);
            split_pack(v2.z, v2.w, Ash[w+5], Asl[w+5]);
            split_pack(v3.x, v3.y, Ash[w+6], Asl[w+6]);
            split_pack(v3.z, v3.w, Ash[w+7], Asl[w+7]);
        }
        {
            const float* src = W + (size_t)(col0 + wr) * K + k0 + wk;
            float4 v0 = *(const float4*)(src);
            float4 v1 = *(const float4*)(src + 4);
            int w = wr * 20 + (wk >> 1);
            split_pack(v0.x, v0.y, Wsh[w+0], Wsl[w+0]);
            split_pack(v0.z, v0.w, Wsh[w+1], Wsl[w+1]);
            split_pack(v1.x, v1.y, Wsh[w+2], Wsl[w+2]);
            split_pack(v1.z, v1.w, Wsh[w+3], Wsl[w+3]);
        }
        __syncthreads();
        #pragma unroll
        for (int ks = 0; ks < 2; ks++) {
            int wb = ks * 8;
            uint32_t ah[2][4], al[2][4], bh[4][2], bl[4][2];
            #pragma unroll
            for (int mi = 0; mi < 2; mi++) {
                int r = wq * 32 + mi * 16;
                ah[mi][0] = Ash[(r + g    ) * 20 + wb + tig];
                ah[mi][1] = Ash[(r + g + 8) * 20 + wb + tig];
                ah[mi][2] = Ash[(r + g    ) * 20 + wb + tig + 4];
                ah[mi][3] = Ash[(r + g + 8) * 20 + wb + tig + 4];
                al[mi][0] = Asl[(r + g    ) * 20 + wb + tig];
                al[mi][1] = Asl[(r + g + 8) * 20 + wb + tig];
                al[mi][2] = Asl[(r + g    ) * 20 + wb + tig + 4];
                al[mi][3] = Asl[(r + g + 8) * 20 + wb + tig + 4];
            }
            #pragma unroll
            for (int n = 0; n < 4; n++) {
                int cc = wn * 32 + n * 8 + g;
                bh[n][0] = Wsh[cc * 20 + wb + tig];
                bh[n][1] = Wsh[cc * 20 + wb + tig + 4];
                bl[n][0] = Wsl[cc * 20 + wb + tig];
                bl[n][1] = Wsl[cc * 20 + wb + tig + 4];
            }
            #pragma unroll
            for (int mi = 0; mi < 2; mi++)
                #pragma unroll
                for (int n = 0; n < 4; n++)
                    mma3(c[mi][n], ah[mi], al[mi], bh[n], bl[n]);
        }
    }
    #pragma unroll
    for (int mi = 0; mi < 2; mi++) {
        #pragma unroll
        for (int n = 0; n < 4; n++) {
            int col = col0 + wn * 32 + n * 8 + 2 * tig;
            float b0 = bias[col], b1 = bias[col + 1];
            int r0 = row0 + wq * 32 + mi * 16 + g;
            *(float2*)&C[(size_t)r0 * N + col] =
                make_float2(c[mi][n][0] + b0, c[mi][n][1] + b1);
            *(float2*)&C[(size_t)(r0 + 8) * N + col] =
                make_float2(c[mi][n][2] + b0, c[mi][n][3] + b1);
        }
    }
}

// ---------------- feature projection -> packed bf16 hi/lo --------------------
// Out[bh][s][f] = sum_d In[b,s,h*64+d] * P[f,d], fp32 math, split at store.
__global__ __launch_bounds__(256) void featproj(
    const float* __restrict__ In,   // [B,S,D]
    const float* __restrict__ P,    // [NF,HD]
    uint32_t* __restrict__ Oh,      // [BH,SEQ,NF/2] packed bf16x2 hi
    uint32_t* __restrict__ Ol)      // lo
{
    __shared__ float Qsm[16][68];   // [d][s]
    __shared__ float Psm[16][68];   // [d][f]
    const int bh = blockIdx.z, b = bh >> 4, h = bh & 15;
    const int s0 = blockIdx.x * 64, f0 = blockIdx.y * 64;
    const int tid = threadIdx.x;
    const int ty = tid >> 4, tx = tid & 15;
    const int lr = tid >> 2;
    const int lk = (tid & 3) << 2;

    const float* qptr = In + ((size_t)(b * SEQ) + s0 + lr) * DMODEL + h * HD + lk;
    const float* pptr = P + (f0 + lr) * HD + lk;

    float c[4][4] = {};   // [s i][f j]
    for (int k0 = 0; k0 < HD; k0 += 16) {
        float4 qv = *(const float4*)(qptr + k0);
        float4 pv = *(const float4*)(pptr + k0);
        Qsm[lk+0][lr] = qv.x; Qsm[lk+1][lr] = qv.y; Qsm[lk+2][lr] = qv.z; Qsm[lk+3][lr] = qv.w;
        Psm[lk+0][lr] = pv.x; Psm[lk+1][lr] = pv.y; Psm[lk+2][lr] = pv.z; Psm[lk+3][lr] = pv.w;
        __syncthreads();
        #pragma unroll
        for (int kk = 0; kk < 16; kk++) {
            float4 a4 = *(const float4*)&Qsm[kk][ty << 2];
            float4 b4 = *(const float4*)&Psm[kk][tx << 2];
            float a_[4] = {a4.x, a4.y, a4.z, a4.w};
            float b_[4] = {b4.x, b4.y, b4.z, b4.w};
            #pragma unroll
            for (int i = 0; i < 4; i++)
                #pragma unroll
                for (int j = 0; j < 4; j++)
                    c[i][j] += a_[i] * b_[j];
        }
        __syncthreads();
    }
    #pragma unroll
    for (int i = 0; i < 4; i++) {
        uint32_t h0, l0, h1, l1;
        split_pack(c[i][0], c[i][1], h0, l0);
        split_pack(c[i][2], c[i][3], h1, l1);
        size_t base = ((size_t)bh * SEQ + s0 + (ty << 2) + i) * (NF / 2)
                      + ((f0 + (tx << 2)) >> 1);
        *(uint2*)&Oh[base] = make_uint2(h0, h1);
        *(uint2*)&Ol[base] = make_uint2(l0, l1);
    }
}

// ---------------- flash attention, bf16x3 MMA, d_eff = NF = 256 --------------
// 64 q x 64 t tiles, full 256-feature K tile resident. 8 warps:
// warp tile = 16q x 32(t|d). 185KB smem, grid (SEQ/64, BH).
#define QT 64
#define TT 64
#define QW 132        // packed words per row: NF/2 + 4
#define VPITCH 68     // fp32
#define PSP 68        // fp32 score pitch
#define PPW 36        // packed P words per row: TT/2 + 4

__global__ __launch_bounds__(256) void attn_bf3(
    const uint32_t* __restrict__ Qh, const uint32_t* __restrict__ Ql,
    const uint32_t* __restrict__ Kh, const uint32_t* __restrict__ Kl,
    const float* __restrict__ V, float* __restrict__ Ctx)
{
    extern __shared__ uint32_t smw[];
    uint32_t* Qsh = smw;                    // QT*QW
    uint32_t* Qsl = Qsh + QT * QW;
    uint32_t* Ksh = Qsl + QT * QW;          // TT*QW
    uint32_t* Ksl = Ksh + TT * QW;
    float*    Vs  = (float*)(Ksl + TT * QW);        // TT*VPITCH
    float*    Ps  = Vs + TT * VPITCH;               // QT*PSP
    uint32_t* Ph  = (uint32_t*)(Ps + QT * PSP);     // QT*PPW
    uint32_t* Pl  = Ph + QT * PPW;
    float* alpha_sm = (float*)(Pl + QT * PPW);      // QT
    float* l_sm = alpha_sm + QT;                    // QT

    const int tid  = threadIdx.x;
    const int lane = tid & 31, warp = tid >> 5;
    const int g = lane >> 2, tig = lane & 3;
    const int wq = warp >> 1, wt = warp & 1;
    const int bh = blockIdx.y, b = bh >> 4, h = bh & 15;
    const int s0 = blockIdx.x * QT;
    const float scale = 0.0625f;   // 1/sqrt(256)

    // load Q tile: QT rows x 128 words, hi+lo
    for (int idx = tid; idx < QT * 32; idx += 256) {
        int r = idx >> 5, w4 = (idx & 31) << 2;
        size_t gb = ((size_t)bh * SEQ + s0 + r) * (NF / 2) + w4;
        *(uint4*)&Qsh[r * QW + w4] = *(const uint4*)&Qh[gb];
        *(uint4*)&Qsl[r * QW + w4] = *(const uint4*)&Ql[gb];
    }

    float o[4][4] = {};
    float m_ = -1e30f, l_ = 0.f;
    const int srow = tid >> 2;          // softmax: 4 threads per row
    const int sc0  = (tid & 3) * 16;

    for (int t0 = 0; t0 < SEQ; t0 += TT) {
        __syncthreads();
        // K tile fill (hi+lo) + V tile fill (fp32)
        for (int idx = tid; idx < TT * 32; idx += 256) {
            int r = idx >> 5, w4 = (idx & 31) << 2;
            size_t gb = ((size_t)bh * SEQ + t0 + r) * (NF / 2) + w4;
            *(uint4*)&Ksh[r * QW + w4] = *(const uint4*)&Kh[gb];
            *(uint4*)&Ksl[r * QW + w4] = *(const uint4*)&Kl[gb];
        }
        for (int idx = tid; idx < TT * 16; idx += 256) {
            int t = idx >> 4, dd = (idx & 15) << 2;
            *(float4*)&Vs[t * VPITCH + dd] =
                *(const float4*)&V[((size_t)b * SEQ + t0 + t) * DMODEL + h * HD + dd];
        }
        __syncthreads();

        // ---- scores: C[64q x 64t] over 256 features ----
        float c[4][4] = {};
        #pragma unroll
        for (int ks = 0; ks < 16; ks++) {
            int wb = ks * 8;
            int ro = wq * 16;
            uint32_t ah[4], al[4], bhf[4][2], blf[4][2];
            ah[0] = Qsh[(ro + g    ) * QW + wb + tig];
            ah[1] = Qsh[(ro + g + 8) * QW + wb + tig];
            ah[2] = Qsh[(ro + g    ) * QW + wb + tig + 4];
            ah[3] = Qsh[(ro + g + 8) * QW + wb + tig + 4];
            al[0] = Qsl[(ro + g    ) * QW + wb + tig];
            al[1] = Qsl[(ro + g + 8) * QW + wb + tig];
            al[2] = Qsl[(ro + g    ) * QW + wb + tig + 4];
            al[3] = Qsl[(ro + g + 8) * QW + wb + tig + 4];
            #pragma unroll
            for (int n = 0; n < 4; n++) {
                int tc = wt * 32 + n * 8 + g;
                bhf[n][0] = Ksh[tc * QW + wb + tig];
                bhf[n][1] = Ksh[tc * QW + wb + tig + 4];
                blf[n][0] = Ksl[tc * QW + wb + tig];
                blf[n][1] = Ksl[tc * QW + wb + tig + 4];
            }
            #pragma unroll
            for (int n = 0; n < 4; n++)
                mma3(c[n], ah, al, bhf[n], blf[n]);
        }
        // stage scores fp32
        #pragma unroll
        for (int n = 0; n < 4; n++) {
            int r = wq * 16 + g;
            int cc = wt * 32 + n * 8 + 2 * tig;
            *(float2*)&Ps[r * PSP + cc] = make_float2(c[n][0], c[n][1]);
            *(float2*)&Ps[(r + 8) * PSP + cc] = make_float2(c[n][2], c[n][3]);
        }
        __syncthreads();

        // ---- online softmax: 4 threads per row, 16 cols each ----
        {
            float vals[16];
            const float4* prow = (const float4*)(Ps + srow * PSP + sc0);
            #pragma unroll
            for (int i = 0; i < 4; i++) {
                float4 v = prow[i];
                vals[i*4+0] = v.x * scale; vals[i*4+1] = v.y * scale;
                vals[i*4+2] = v.z * scale; vals[i*4+3] = v.w * scale;
            }
            float mx = -1e30f;
            #pragma unroll
            for (int i = 0; i < 16; i++) mx = fmaxf(mx, vals[i]);
            mx = fmaxf(mx, __shfl_xor_sync(0xffffffffu, mx, 1));
            mx = fmaxf(mx, __shfl_xor_sync(0xffffffffu, mx, 2));
            float mn = fmaxf(m_, mx);
            float alpha = __expf(m_ - mn);
            float sum = 0.f;
            #pragma unroll
            for (int i = 0; i < 16; i++) { vals[i] = __expf(vals[i] - mn); sum += vals[i]; }
            sum += __shfl_xor_sync(0xffffffffu, sum, 1);
            sum += __shfl_xor_sync(0xffffffffu, sum, 2);
            l_ = l_ * alpha + sum; m_ = mn;
            // pack P hi/lo
            #pragma unroll
            for (int i = 0; i < 8; i++) {
                uint32_t hw, lw;
                split_pack(vals[2*i], vals[2*i+1], hw, lw);
                Ph[srow * PPW + (tid & 3) * 8 + i] = hw;
                Pl[srow * PPW + (tid & 3) * 8 + i] = lw;
            }
            if ((tid & 3) == 0) alpha_sm[srow] = alpha;
        }
        __syncthreads();

        // rescale O
        {
            float a0 = alpha_sm[wq * 16 + g], a8 = alpha_sm[wq * 16 + g + 8];
            #pragma unroll
            for (int n = 0; n < 4; n++) {
                o[n][0] *= a0; o[n][1] *= a0;
                o[n][2] *= a8; o[n][3] *= a8;
            }
        }
        // ---- O += P @ V ----
        #pragma unroll
        for (int ks = 0; ks < 4; ks++) {
            int wb = ks * 8;
            int ro = wq * 16;
            uint32_t ah[4], al[4], bhf[4][2], blf[4][2];
            ah[0] = Ph[(ro + g    ) * PPW + wb + tig];
            ah[1] = Ph[(ro + g + 8) * PPW + wb + tig];
            ah[2] = Ph[(ro + g    ) * PPW + wb + tig + 4];
            ah[3] = Ph[(ro + g + 8) * PPW + wb + tig + 4];
            al[0] = Pl[(ro + g    ) * PPW + wb + tig];
            al[1] = Pl[(ro + g + 8) * PPW + wb + tig];
            al[2] = Pl[(ro + g    ) * PPW + wb + tig + 4];
            al[3] = Pl[(ro + g + 8) * PPW + wb + tig + 4];
            int t00 = ks * 16 + 2 * tig;
            #pragma unroll
            for (int n = 0; n < 4; n++) {
                int d = wt * 32 + n * 8 + g;
                float v0 = Vs[(t00    ) * VPITCH + d];
                float v1 = Vs[(t00 + 1) * VPITCH + d];
                float v2 = Vs[(t00 + 8) * VPITCH + d];
                float v3 = Vs[(t00 + 9) * VPITCH + d];
                split_pack(v0, v1, bhf[n][0], blf[n][0]);
                split_pack(v2, v3, bhf[n][1], blf[n][1]);
            }
            #pragma unroll
            for (int n = 0; n < 4; n++)
                mma3(o[n], ah, al, bhf[n], blf[n]);
        }
    }
    if ((tid & 3) == 0) l_sm[srow] = l_;
    __syncthreads();
    #pragma unroll
    for (int n = 0; n < 4; n++) {
        int r = wq * 16 + g;
        int dc = wt * 32 + n * 8 + 2 * tig;
        float inv0 = 1.0f / l_sm[r], inv8 = 1.0f / l_sm[r + 8];
        *(float2*)&Ctx[((size_t)b * SEQ + s0 + r) * DMODEL + h * HD + dc] =
            make_float2(o[n][0] * inv0, o[n][1] * inv0);
        *(float2*)&Ctx[((size_t)b * SEQ + s0 + r + 8) * DMODEL + h * HD + dc] =
            make_float2(o[n][2] * inv8, o[n][3] * inv8);
    }
}

// ---------------- launch ------------------------------------------------------
extern "C" void kernel_launch(void* const* d_in, const int* in_sizes, int n_in,
                              void* d_out, int out_size)
{
    (void)in_sizes; (void)n_in; (void)out_size;
    const float* x  = (const float*)d_in[0];
    const float* Wq = (const float*)d_in[1];
    const float* bq = (const float*)d_in[2];
    const float* Wk = (const float*)d_in[3];
    const float* bk = (const float*)d_in[4];
    const float* Wv = (const float*)d_in[5];
    const float* bv = (const float*)d_in[6];
    const float* Wo = (const float*)d_in[7];
    const float* bo = (const float*)d_in[8];
    const float* P  = (const float*)d_in[9];

    float *q, *k, *v, *ctx;
    uint32_t *qph, *qpl, *kph, *kpl;
    cudaGetSymbolAddress((void**)&q,   g_q);
    cudaGetSymbolAddress((void**)&k,   g_k);
    cudaGetSymbolAddress((void**)&v,   g_v);
    cudaGetSymbolAddress((void**)&ctx, g_ctx);
    cudaGetSymbolAddress((void**)&qph, g_qph);
    cudaGetSymbolAddress((void**)&qpl, g_qpl);
    cudaGetSymbolAddress((void**)&kph, g_kph);
    cudaGetSymbolAddress((void**)&kpl, g_kpl);

    dim3 gemm_grid(DMODEL / 64, MROWS / 128);   // (16, 64)
    gemm_bf3<<<gemm_grid, 256>>>(x, Wq, bq, q, DMODEL, DMODEL);
    gemm_bf3<<<gemm_grid, 256>>>(x, Wk, bk, k, DMODEL, DMODEL);
    gemm_bf3<<<gemm_grid, 256>>>(x, Wv, bv, v, DMODEL, DMODEL);

    dim3 fp_grid(SEQ / 64, NF / 64, BH);        // (32, 4, 128)
    featproj<<<fp_grid, 256>>>(q, P, qph, qpl);
    featproj<<<fp_grid, 256>>>(k, P, kph, kpl);

    const int ATT_SMEM = (QT * QW * 2 + TT * QW * 2 + TT * VPITCH + QT * PSP
                          + QT * PPW * 2 + 2 * QT) * 4;   // 188,928 B
    cudaFuncSetAttribute(attn_bf3, cudaFuncAttributeMaxDynamicSharedMemorySize, ATT_SMEM);
    attn_bf3<<<dim3(SEQ / QT, BH), 256, ATT_SMEM>>>(qph, qpl, kph, kpl, v, ctx);

    gemm_bf3<<<gemm_grid, 256>>>(ctx, Wo, bo, (float*)d_out, DMODEL, DMODEL);
}

// round 7
// speedup vs baseline: 1.8045x; 1.2502x over previous
#include <cuda_runtime.h>
#include <cuda_bf16.h>
#include <math.h>
#include <stdint.h>

#define BATCH  4
#define SEQ    2048
#define DMODEL 1024
#define NHEADS 16
#define HD     64
#define NF     256
#define BH     (BATCH*NHEADS)       // 128
#define MROWS  (BATCH*SEQ)          // 8192

// ---------------- scratch (static device globals; no allocations) ------------
__device__ float g_q  [MROWS*DMODEL];   // [B,S,D]
__device__ float g_k  [MROWS*DMODEL];
__device__ float g_v  [MROWS*DMODEL];
__device__ float g_ctx[MROWS*DMODEL];
// packed bf16x2 hi/lo feature projections, [BH][SEQ][NF/2] words
__device__ uint32_t g_qph[(size_t)BH*SEQ*(NF/2)];
__device__ uint32_t g_qpl[(size_t)BH*SEQ*(NF/2)];
__device__ uint32_t g_kph[(size_t)BH*SEQ*(NF/2)];
__device__ uint32_t g_kpl[(size_t)BH*SEQ*(NF/2)];

// ---------------- helpers ----------------------------------------------------
__device__ __forceinline__ void split_pack(float x, float y, uint32_t& hi, uint32_t& lo) {
    __nv_bfloat162 h = __floats2bfloat162_rn(x, y);
    float hx = __bfloat162float(h.x);
    float hy = __bfloat162float(h.y);
    __nv_bfloat162 l = __floats2bfloat162_rn(x - hx, y - hy);
    hi = *reinterpret_cast<uint32_t*>(&h);
    lo = *reinterpret_cast<uint32_t*>(&l);
}

__device__ __forceinline__ void mma16(float* c, const uint32_t* a, const uint32_t* b) {
    asm volatile(
        "mma.sync.aligned.m16n8k16.row.col.f32.bf16.bf16.f32 "
        "{%0,%1,%2,%3}, {%4,%5,%6,%7}, {%8,%9}, {%0,%1,%2,%3};\n"
        : "+f"(c[0]), "+f"(c[1]), "+f"(c[2]), "+f"(c[3])
        : "r"(a[0]), "r"(a[1]), "r"(a[2]), "r"(a[3]), "r"(b[0]), "r"(b[1]));
}
__device__ __forceinline__ void mma3(float* c, const uint32_t* ah, const uint32_t* al,
                                     const uint32_t* bh, const uint32_t* bl) {
    mma16(c, ah, bl);
    mma16(c, al, bh);
    mma16(c, ah, bh);
}

__device__ __forceinline__ void ldsm4(uint32_t& r0, uint32_t& r1, uint32_t& r2,
                                      uint32_t& r3, uint32_t addr) {
    asm volatile("ldmatrix.sync.aligned.m8n8.x4.shared.b16 {%0,%1,%2,%3}, [%4];"
        : "=r"(r0), "=r"(r1), "=r"(r2), "=r"(r3) : "r"(addr));
}
__device__ __forceinline__ uint32_t s2u(const void* p) {
    uint32_t a;
    asm("{ .reg .u64 t; cvta.to.shared.u64 t, %1; cvt.u32.u64 %0, t; }" : "=r"(a) : "l"(p));
    return a;
}

// ---------------- bf16x3 GEMM: C[M,N] = A[M,K] @ W[N,K]^T + b ----------------
// Block tile 128x64, 8 warps of 32x32, BK=32. Split at smem-fill time.
// Packed word pitch 20 (16 data + 4 pad) => conflict-free ldmatrix phases.
__global__ __launch_bounds__(256) void gemm_bf3(
    const float* __restrict__ A, const float* __restrict__ W,
    const float* __restrict__ bias, float* __restrict__ C,
    int N, int K)
{
    __shared__ uint32_t Ash[128 * 20], Asl[128 * 20];
    __shared__ uint32_t Wsh[64 * 20],  Wsl[64 * 20];
    const int tid  = threadIdx.x;
    const int lane = tid & 31, warp = tid >> 5;
    const int g = lane >> 2, tig = lane & 3;
    const int wq = warp >> 1, wn = warp & 1;
    const int row0 = blockIdx.y * 128, col0 = blockIdx.x * 64;

    const int ar = tid >> 1, ak = (tid & 1) * 16;
    const int wr = tid >> 2, wk = (tid & 3) * 8;

    // ldmatrix per-lane byte offsets
    const int arow = ((lane >> 3) & 1) * 8 + (lane & 7);
    const int acol = (lane >> 4) * 4;
    const int brow = (lane >> 4) * 8 + (lane & 7);
    const int bcol = ((lane >> 3) & 1) * 4;
    uint32_t aOffH[2], aOffL[2], bOffH[2], bOffL[2];
    {
        uint32_t AshU = s2u(Ash), AslU = s2u(Asl), WshU = s2u(Wsh), WslU = s2u(Wsl);
        #pragma unroll
        for (int mi = 0; mi < 2; mi++) {
            uint32_t off = ((wq * 32 + mi * 16 + arow) * 20 + acol) * 4;
            aOffH[mi] = AshU + off;
            aOffL[mi] = AslU + off;
        }
        #pragma unroll
        for (int jj = 0; jj < 2; jj++) {
            uint32_t off = ((wn * 32 + jj * 16 + brow) * 20 + bcol) * 4;
            bOffH[jj] = WshU + off;
            bOffL[jj] = WslU + off;
        }
    }

    float c[2][4][4] = {};

    for (int k0 = 0; k0 < K; k0 += 32) {
        __syncthreads();
        {
            const float* src = A + (size_t)(row0 + ar) * K + k0 + ak;
            float4 v0 = *(const float4*)(src);
            float4 v1 = *(const float4*)(src + 4);
            float4 v2 = *(const float4*)(src + 8);
            float4 v3 = *(const float4*)(src + 12);
            int w = ar * 20 + (ak >> 1);
            split_pack(v0.x, v0.y, Ash[w+0], Asl[w+0]);
            split_pack(v0.z, v0.w, Ash[w+1], Asl[w+1]);
            split_pack(v1.x, v1.y, Ash[w+2], Asl[w+2]);
            split_pack(v1.z, v1.w, Ash[w+3], Asl[w+3]);
            split_pack(v2.x, v2.y, Ash[w+4], Asl[w+4]);
            split_pack(v2.z, v2.w, Ash[w+5], Asl[w+5]);
            split_pack(v3.x, v3.y, Ash[w+6], Asl[w+6]);
            split_pack(v3.z, v3.w, Ash[w+7], Asl[w+7]);
        }
        {
            const float* src = W + (size_t)(col0 + wr) * K + k0 + wk;
            float4 v0 = *(const float4*)(src);
            float4 v1 = *(const float4*)(src + 4);
            int w = wr * 20 + (wk >> 1);
            split_pack(v0.x, v0.y, Wsh[w+0], Wsl[w+0]);
            split_pack(v0.z, v0.w, Wsh[w+1], Wsl[w+1]);
            split_pack(v1.x, v1.y, Wsh[w+2], Wsl[w+2]);
            split_pack(v1.z, v1.w, Wsh[w+3], Wsl[w+3]);
        }
        __syncthreads();
        #pragma unroll
        for (int ks = 0; ks < 2; ks++) {
            uint32_t wbb = ks * 32;   // 8 words
            uint32_t ah[2][4], al[2][4], bh[4][2], bl[4][2];
            #pragma unroll
            for (int mi = 0; mi < 2; mi++) {
                ldsm4(ah[mi][0], ah[mi][1], ah[mi][2], ah[mi][3], aOffH[mi] + wbb);
                ldsm4(al[mi][0], al[mi][1], al[mi][2], al[mi][3], aOffL[mi] + wbb);
            }
            #pragma unroll
            for (int jj = 0; jj < 2; jj++) {
                ldsm4(bh[jj*2][0], bh[jj*2][1], bh[jj*2+1][0], bh[jj*2+1][1], bOffH[jj] + wbb);
                ldsm4(bl[jj*2][0], bl[jj*2][1], bl[jj*2+1][0], bl[jj*2+1][1], bOffL[jj] + wbb);
            }
            #pragma unroll
            for (int mi = 0; mi < 2; mi++)
                #pragma unroll
                for (int n = 0; n < 4; n++)
                    mma3(c[mi][n], ah[mi], al[mi], bh[n], bl[n]);
        }
    }
    #pragma unroll
    for (int mi = 0; mi < 2; mi++) {
        #pragma unroll
        for (int n = 0; n < 4; n++) {
            int col = col0 + wn * 32 + n * 8 + 2 * tig;
            float b0 = bias[col], b1 = bias[col + 1];
            int r0 = row0 + wq * 32 + mi * 16 + g;
            *(float2*)&C[(size_t)r0 * N + col] =
                make_float2(c[mi][n][0] + b0, c[mi][n][1] + b1);
            *(float2*)&C[(size_t)(r0 + 8) * N + col] =
                make_float2(c[mi][n][2] + b0, c[mi][n][3] + b1);
        }
    }
}

// ---------------- feature projection -> packed bf16 hi/lo --------------------
__global__ __launch_bounds__(256) void featproj(
    const float* __restrict__ In, const float* __restrict__ P,
    uint32_t* __restrict__ Oh, uint32_t* __restrict__ Ol)
{
    __shared__ float Qsm[16][68];
    __shared__ float Psm[16][68];
    const int bh = blockIdx.z, b = bh >> 4, h = bh & 15;
    const int s0 = blockIdx.x * 64, f0 = blockIdx.y * 64;
    const int tid = threadIdx.x;
    const int ty = tid >> 4, tx = tid & 15;
    const int lr = tid >> 2;
    const int lk = (tid & 3) << 2;

    const float* qptr = In + ((size_t)(b * SEQ) + s0 + lr) * DMODEL + h * HD + lk;
    const float* pptr = P + (f0 + lr) * HD + lk;

    float c[4][4] = {};
    for (int k0 = 0; k0 < HD; k0 += 16) {
        float4 qv = *(const float4*)(qptr + k0);
        float4 pv = *(const float4*)(pptr + k0);
        Qsm[lk+0][lr] = qv.x; Qsm[lk+1][lr] = qv.y; Qsm[lk+2][lr] = qv.z; Qsm[lk+3][lr] = qv.w;
        Psm[lk+0][lr] = pv.x; Psm[lk+1][lr] = pv.y; Psm[lk+2][lr] = pv.z; Psm[lk+3][lr] = pv.w;
        __syncthreads();
        #pragma unroll
        for (int kk = 0; kk < 16; kk++) {
            float4 a4 = *(const float4*)&Qsm[kk][ty << 2];
            float4 b4 = *(const float4*)&Psm[kk][tx << 2];
            float a_[4] = {a4.x, a4.y, a4.z, a4.w};
            float b_[4] = {b4.x, b4.y, b4.z, b4.w};
            #pragma unroll
            for (int i = 0; i < 4; i++)
                #pragma unroll
                for (int j = 0; j < 4; j++)
                    c[i][j] += a_[i] * b_[j];
        }
        __syncthreads();
    }
    #pragma unroll
    for (int i = 0; i < 4; i++) {
        uint32_t h0, l0, h1, l1;
        split_pack(c[i][0], c[i][1], h0, l0);
        split_pack(c[i][2], c[i][3], h1, l1);
        size_t base = ((size_t)bh * SEQ + s0 + (ty << 2) + i) * (NF / 2)
                      + ((f0 + (tx << 2)) >> 1);
        *(uint2*)&Oh[base] = make_uint2(h0, h1);
        *(uint2*)&Ol[base] = make_uint2(l0, l1);
    }
}

// ---------------- flash attention, bf16x3 MMA + ldmatrix ---------------------
// 64 q x 64 t tiles, full 256-feature K tile resident. 8 warps:
// warp tile = 16q x 32(t|d).
#define QT 64
#define TT 64
#define QW 132        // packed words per row: NF/2 + 4
#define VTW 36        // V^T packed words per d-row: TT/2 + 4
#define PSP 68        // fp32 score pitch
#define PPW 36        // packed P words per row: TT/2 + 4

__global__ __launch_bounds__(256) void attn_bf3(
    const uint32_t* __restrict__ Qh, const uint32_t* __restrict__ Ql,
    const uint32_t* __restrict__ Kh, const uint32_t* __restrict__ Kl,
    const float* __restrict__ V, float* __restrict__ Ctx)
{
    extern __shared__ uint32_t smw[];
    uint32_t* Qsh = smw;                    // QT*QW
    uint32_t* Qsl = Qsh + QT * QW;
    uint32_t* Ksh = Qsl + QT * QW;          // TT*QW
    uint32_t* Ksl = Ksh + TT * QW;
    uint32_t* VtH = Ksl + TT * QW;          // 64 d-rows * VTW
    uint32_t* VtL = VtH + 64 * VTW;
    float*    Ps  = (float*)(VtL + 64 * VTW);       // QT*PSP
    uint32_t* Ph  = (uint32_t*)(Ps + QT * PSP);     // QT*PPW
    uint32_t* Pl  = Ph + QT * PPW;
    float* alpha_sm = (float*)(Pl + QT * PPW);      // QT
    float* l_sm = alpha_sm + QT;                    // QT

    const int tid  = threadIdx.x;
    const int lane = tid & 31, warp = tid >> 5;
    const int g = lane >> 2, tig = lane & 3;
    const int wq = warp >> 1, wt = warp & 1;
    const int bh = blockIdx.y, b = bh >> 4, h = bh & 15;
    const int s0 = blockIdx.x * QT;
    const float scale = 0.0625f;   // 1/sqrt(256)

    // ldmatrix per-lane byte offsets
    const int arow = ((lane >> 3) & 1) * 8 + (lane & 7);
    const int acol = (lane >> 4) * 4;
    const int brow = (lane >> 4) * 8 + (lane & 7);
    const int bcol = ((lane >> 3) & 1) * 4;
    const uint32_t qA_h = s2u(Qsh) + ((wq * 16 + arow) * QW + acol) * 4;
    const uint32_t qA_l = s2u(Qsl) + ((wq * 16 + arow) * QW + acol) * 4;
    uint32_t kB_h[2], kB_l[2], vB_h[2], vB_l[2];
    #pragma unroll
    for (int jj = 0; jj < 2; jj++) {
        uint32_t koff = ((wt * 32 + jj * 16 + brow) * QW + bcol) * 4;
        kB_h[jj] = s2u(Ksh) + koff;
        kB_l[jj] = s2u(Ksl) + koff;
        uint32_t voff = ((wt * 32 + jj * 16 + brow) * VTW + bcol) * 4;
        vB_h[jj] = s2u(VtH) + voff;
        vB_l[jj] = s2u(VtL) + voff;
    }
    const uint32_t pA_h = s2u(Ph) + ((wq * 16 + arow) * PPW + acol) * 4;
    const uint32_t pA_l = s2u(Pl) + ((wq * 16 + arow) * PPW + acol) * 4;

    // load Q tile: QT rows x 128 words, hi+lo
    for (int idx = tid; idx < QT * 32; idx += 256) {
        int r = idx >> 5, w4 = (idx & 31) << 2;
        size_t gb = ((size_t)bh * SEQ + s0 + r) * (NF / 2) + w4;
        *(uint4*)&Qsh[r * QW + w4] = *(const uint4*)&Qh[gb];
        *(uint4*)&Qsl[r * QW + w4] = *(const uint4*)&Ql[gb];
    }

    float o[4][4] = {};
    float m_ = -1e30f, l_ = 0.f;
    const int srow = tid >> 2;          // softmax: 4 threads per row
    const int sc0  = (tid & 3) * 16;

    for (int t0 = 0; t0 < SEQ; t0 += TT) {
        __syncthreads();
        // K tile fill (hi+lo)
        for (int idx = tid; idx < TT * 32; idx += 256) {
            int r = idx >> 5, w4 = (idx & 31) << 2;
            size_t gb = ((size_t)bh * SEQ + t0 + r) * (NF / 2) + w4;
            *(uint4*)&Ksh[r * QW + w4] = *(const uint4*)&Kh[gb];
            *(uint4*)&Ksl[r * QW + w4] = *(const uint4*)&Kl[gb];
        }
        // V^T pre-split fill: word (d, t/2) = bf16x2(v[t][d], v[t+1][d])
        for (int idx = tid; idx < TT * 16; idx += 256) {
            int t = idx >> 4, d4 = (idx & 15) << 2;
            float4 v = *(const float4*)&V[((size_t)b * SEQ + t0 + t) * DMODEL + h * HD + d4];
            float4 p;
            p.x = __shfl_xor_sync(0xffffffffu, v.x, 16);
            p.y = __shfl_xor_sync(0xffffffffu, v.y, 16);
            p.z = __shfl_xor_sync(0xffffffffu, v.z, 16);
            p.w = __shfl_xor_sync(0xffffffffu, v.w, 16);
            float ve[4], vo[4];
            if (t & 1) {
                ve[0]=p.x; ve[1]=p.y; ve[2]=p.z; ve[3]=p.w;
                vo[0]=v.x; vo[1]=v.y; vo[2]=v.z; vo[3]=v.w;
            } else {
                ve[0]=v.x; ve[1]=v.y; ve[2]=v.z; ve[3]=v.w;
                vo[0]=p.x; vo[1]=p.y; vo[2]=p.z; vo[3]=p.w;
            }
            int i0 = (t & 1) ? 2 : 0;
            int tw = t >> 1;
            #pragma unroll
            for (int i = 0; i < 2; i++) {
                uint32_t hw, lw;
                split_pack(ve[i0 + i], vo[i0 + i], hw, lw);
                VtH[(d4 + i0 + i) * VTW + tw] = hw;
                VtL[(d4 + i0 + i) * VTW + tw] = lw;
            }
        }
        __syncthreads();

        // ---- scores: C[64q x 64t] over 256 features ----
        float c[4][4] = {};
        #pragma unroll
        for (int ks = 0; ks < 16; ks++) {
            uint32_t wbb = ks * 32;   // 8 words
            uint32_t ah[4], al[4], bhf[4][2], blf[4][2];
            ldsm4(ah[0], ah[1], ah[2], ah[3], qA_h + wbb);
            ldsm4(al[0], al[1], al[2], al[3], qA_l + wbb);
            #pragma unroll
            for (int jj = 0; jj < 2; jj++) {
                ldsm4(bhf[jj*2][0], bhf[jj*2][1], bhf[jj*2+1][0], bhf[jj*2+1][1], kB_h[jj] + wbb);
                ldsm4(blf[jj*2][0], blf[jj*2][1], blf[jj*2+1][0], blf[jj*2+1][1], kB_l[jj] + wbb);
            }
            #pragma unroll
            for (int n = 0; n < 4; n++)
                mma3(c[n], ah, al, bhf[n], blf[n]);
        }
        // stage scores fp32
        #pragma unroll
        for (int n = 0; n < 4; n++) {
            int r = wq * 16 + g;
            int cc = wt * 32 + n * 8 + 2 * tig;
            *(float2*)&Ps[r * PSP + cc] = make_float2(c[n][0], c[n][1]);
            *(float2*)&Ps[(r + 8) * PSP + cc] = make_float2(c[n][2], c[n][3]);
        }
        __syncthreads();

        // ---- online softmax: 4 threads per row, 16 cols each ----
        {
            float vals[16];
            const float4* prow = (const float4*)(Ps + srow * PSP + sc0);
            #pragma unroll
            for (int i = 0; i < 4; i++) {
                float4 v = prow[i];
                vals[i*4+0] = v.x * scale; vals[i*4+1] = v.y * scale;
                vals[i*4+2] = v.z * scale; vals[i*4+3] = v.w * scale;
            }
            float mx = -1e30f;
            #pragma unroll
            for (int i = 0; i < 16; i++) mx = fmaxf(mx, vals[i]);
            mx = fmaxf(mx, __shfl_xor_sync(0xffffffffu, mx, 1));
            mx = fmaxf(mx, __shfl_xor_sync(0xffffffffu, mx, 2));
            float mn = fmaxf(m_, mx);
            float alpha = __expf(m_ - mn);
            float sum = 0.f;
            #pragma unroll
            for (int i = 0; i < 16; i++) { vals[i] = __expf(vals[i] - mn); sum += vals[i]; }
            sum += __shfl_xor_sync(0xffffffffu, sum, 1);
            sum += __shfl_xor_sync(0xffffffffu, sum, 2);
            l_ = l_ * alpha + sum; m_ = mn;
            #pragma unroll
            for (int i = 0; i < 8; i++) {
                uint32_t hw, lw;
                split_pack(vals[2*i], vals[2*i+1], hw, lw);
                Ph[srow * PPW + (tid & 3) * 8 + i] = hw;
                Pl[srow * PPW + (tid & 3) * 8 + i] = lw;
            }
            if ((tid & 3) == 0) alpha_sm[srow] = alpha;
        }
        __syncthreads();

        // rescale O
        {
            float a0 = alpha_sm[wq * 16 + g], a8 = alpha_sm[wq * 16 + g + 8];
            #pragma unroll
            for (int n = 0; n < 4; n++) {
                o[n][0] *= a0; o[n][1] *= a0;
                o[n][2] *= a8; o[n][3] *= a8;
            }
        }
        // ---- O += P @ V ----
        #pragma unroll
        for (int ks = 0; ks < 4; ks++) {
            uint32_t wbb = ks * 32;
            uint32_t ah[4], al[4], bhf[4][2], blf[4][2];
            ldsm4(ah[0], ah[1], ah[2], ah[3], pA_h + wbb);
            ldsm4(al[0], al[1], al[2], al[3], pA_l + wbb);
            #pragma unroll
            for (int jj = 0; jj < 2; jj++) {
                ldsm4(bhf[jj*2][0], bhf[jj*2][1], bhf[jj*2+1][0], bhf[jj*2+1][1], vB_h[jj] + wbb);
                ldsm4(blf[jj*2][0], blf[jj*2][1], blf[jj*2+1][0], blf[jj*2+1][1], vB_l[jj] + wbb);
            }
            #pragma unroll
            for (int n = 0; n < 4; n++)
                mma3(o[n], ah, al, bhf[n], blf[n]);
        }
    }
    if ((tid & 3) == 0) l_sm[srow] = l_;
    __syncthreads();
    #pragma unroll
    for (int n = 0; n < 4; n++) {
        int r = wq * 16 + g;
        int dc = wt * 32 + n * 8 + 2 * tig;
        float inv0 = 1.0f / l_sm[r], inv8 = 1.0f / l_sm[r + 8];
        *(float2*)&Ctx[((size_t)b * SEQ + s0 + r) * DMODEL + h * HD + dc] =
            make_float2(o[n][0] * inv0, o[n][1] * inv0);
        *(float2*)&Ctx[((size_t)b * SEQ + s0 + r + 8) * DMODEL + h * HD + dc] =
            make_float2(o[n][2] * inv8, o[n][3] * inv8);
    }
}

// ---------------- launch ------------------------------------------------------
extern "C" void kernel_launch(void* const* d_in, const int* in_sizes, int n_in,
                              void* d_out, int out_size)
{
    (void)in_sizes; (void)n_in; (void)out_size;
    const float* x  = (const float*)d_in[0];
    const float* Wq = (const float*)d_in[1];
    const float* bq = (const float*)d_in[2];
    const float* Wk = (const float*)d_in[3];
    const float* bk = (const float*)d_in[4];
    const float* Wv = (const float*)d_in[5];
    const float* bv = (const float*)d_in[6];
    const float* Wo = (const float*)d_in[7];
    const float* bo = (const float*)d_in[8];
    const float* P  = (const float*)d_in[9];

    float *q, *k, *v, *ctx;
    uint32_t *qph, *qpl, *kph, *kpl;
    cudaGetSymbolAddress((void**)&q,   g_q);
    cudaGetSymbolAddress((void**)&k,   g_k);
    cudaGetSymbolAddress((void**)&v,   g_v);
    cudaGetSymbolAddress((void**)&ctx, g_ctx);
    cudaGetSymbolAddress((void**)&qph, g_qph);
    cudaGetSymbolAddress((void**)&qpl, g_qpl);
    cudaGetSymbolAddress((void**)&kph, g_kph);
    cudaGetSymbolAddress((void**)&kpl, g_kpl);

    dim3 gemm_grid(DMODEL / 64, MROWS / 128);   // (16, 64)
    gemm_bf3<<<gemm_grid, 256>>>(x, Wq, bq, q, DMODEL, DMODEL);
    gemm_bf3<<<gemm_grid, 256>>>(x, Wk, bk, k, DMODEL, DMODEL);
    gemm_bf3<<<gemm_grid, 256>>>(x, Wv, bv, v, DMODEL, DMODEL);

    dim3 fp_grid(SEQ / 64, NF / 64, BH);        // (32, 4, 128)
    featproj<<<fp_grid, 256>>>(q, P, qph, qpl);
    featproj<<<fp_grid, 256>>>(k, P, kph, kpl);

    const int ATT_SMEM = (QT * QW * 2 + TT * QW * 2 + 64 * VTW * 2 + QT * PSP
                          + QT * PPW * 2 + 2 * QT) * 4;   // ~190KB
    cudaFuncSetAttribute(attn_bf3, cudaFuncAttributeMaxDynamicSharedMemorySize, ATT_SMEM);
    attn_bf3<<<dim3(SEQ / QT, BH), 256, ATT_SMEM>>>(qph, qpl, kph, kpl, v, ctx);

    gemm_bf3<<<gemm_grid, 256>>>(ctx, Wo, bo, (float*)d_out, DMODEL, DMODEL);
}

// round 8
// speedup vs baseline: 2.4473x; 1.3562x over previous
#include <cuda_runtime.h>
#include <cuda_bf16.h>
#include <math.h>
#include <stdint.h>

#define BATCH  4
#define SEQ    2048
#define DMODEL 1024
#define NHEADS 16
#define HD     64
#define NF     256
#define BH     (BATCH*NHEADS)       // 128
#define MROWS  (BATCH*SEQ)          // 8192

// ---------------- scratch (static device globals; no allocations) ------------
__device__ float g_q  [MROWS*DMODEL];   // [B,S,D]
__device__ float g_k  [MROWS*DMODEL];
__device__ float g_v  [MROWS*DMODEL];
__device__ float g_ctx[MROWS*DMODEL];
// packed bf16x2 hi/lo feature projections, [BH][SEQ][NF/2] words
__device__ uint32_t g_qph[(size_t)BH*SEQ*(NF/2)];
__device__ uint32_t g_qpl[(size_t)BH*SEQ*(NF/2)];
__device__ uint32_t g_kph[(size_t)BH*SEQ*(NF/2)];
__device__ uint32_t g_kpl[(size_t)BH*SEQ*(NF/2)];

// ---------------- helpers ----------------------------------------------------
__device__ __forceinline__ void split_pack(float x, float y, uint32_t& hi, uint32_t& lo) {
    __nv_bfloat162 h = __floats2bfloat162_rn(x, y);
    float hx = __bfloat162float(h.x);
    float hy = __bfloat162float(h.y);
    __nv_bfloat162 l = __floats2bfloat162_rn(x - hx, y - hy);
    hi = *reinterpret_cast<uint32_t*>(&h);
    lo = *reinterpret_cast<uint32_t*>(&l);
}

__device__ __forceinline__ void mma16(float* c, const uint32_t* a, const uint32_t* b) {
    asm volatile(
        "mma.sync.aligned.m16n8k16.row.col.f32.bf16.bf16.f32 "
        "{%0,%1,%2,%3}, {%4,%5,%6,%7}, {%8,%9}, {%0,%1,%2,%3};\n"
        : "+f"(c[0]), "+f"(c[1]), "+f"(c[2]), "+f"(c[3])
        : "r"(a[0]), "r"(a[1]), "r"(a[2]), "r"(a[3]), "r"(b[0]), "r"(b[1]));
}
__device__ __forceinline__ void mma3(float* c, const uint32_t* ah, const uint32_t* al,
                                     const uint32_t* bh, const uint32_t* bl) {
    mma16(c, ah, bl);
    mma16(c, al, bh);
    mma16(c, ah, bh);
}

__device__ __forceinline__ void ldsm4(uint32_t& r0, uint32_t& r1, uint32_t& r2,
                                      uint32_t& r3, uint32_t addr) {
    asm volatile("ldmatrix.sync.aligned.m8n8.x4.shared.b16 {%0,%1,%2,%3}, [%4];"
        : "=r"(r0), "=r"(r1), "=r"(r2), "=r"(r3) : "r"(addr));
}
__device__ __forceinline__ uint32_t s2u(const void* p) {
    uint32_t a;
    asm("{ .reg .u64 t; cvta.to.shared.u64 t, %1; cvt.u32.u64 %0, t; }" : "=r"(a) : "l"(p));
    return a;
}

// ---------------- bf16x3 GEMM (unchanged, known-good) ------------------------
__global__ __launch_bounds__(256) void gemm_bf3(
    const float* __restrict__ A, const float* __restrict__ W,
    const float* __restrict__ bias, float* __restrict__ C,
    int N, int K)
{
    __shared__ uint32_t Ash[128 * 20], Asl[128 * 20];
    __shared__ uint32_t Wsh[64 * 20],  Wsl[64 * 20];
    const int tid  = threadIdx.x;
    const int lane = tid & 31, warp = tid >> 5;
    const int g = lane >> 2, tig = lane & 3;
    const int wq = warp >> 1, wn = warp & 1;
    const int row0 = blockIdx.y * 128, col0 = blockIdx.x * 64;

    const int ar = tid >> 1, ak = (tid & 1) * 16;
    const int wr = tid >> 2, wk = (tid & 3) * 8;

    const int arow = ((lane >> 3) & 1) * 8 + (lane & 7);
    const int acol = (lane >> 4) * 4;
    const int brow = (lane >> 4) * 8 + (lane & 7);
    const int bcol = ((lane >> 3) & 1) * 4;
    uint32_t aOffH[2], aOffL[2], bOffH[2], bOffL[2];
    {
        uint32_t AshU = s2u(Ash), AslU = s2u(Asl), WshU = s2u(Wsh), WslU = s2u(Wsl);
        #pragma unroll
        for (int mi = 0; mi < 2; mi++) {
            uint32_t off = ((wq * 32 + mi * 16 + arow) * 20 + acol) * 4;
            aOffH[mi] = AshU + off;
            aOffL[mi] = AslU + off;
        }
        #pragma unroll
        for (int jj = 0; jj < 2; jj++) {
            uint32_t off = ((wn * 32 + jj * 16 + brow) * 20 + bcol) * 4;
            bOffH[jj] = WshU + off;
            bOffL[jj] = WslU + off;
        }
    }

    float c[2][4][4] = {};

    for (int k0 = 0; k0 < K; k0 += 32) {
        __syncthreads();
        {
            const float* src = A + (size_t)(row0 + ar) * K + k0 + ak;
            float4 v0 = *(const float4*)(src);
            float4 v1 = *(const float4*)(src + 4);
            float4 v2 = *(const float4*)(src + 8);
            float4 v3 = *(const float4*)(src + 12);
            int w = ar * 20 + (ak >> 1);
            split_pack(v0.x, v0.y, Ash[w+0], Asl[w+0]);
            split_pack(v0.z, v0.w, Ash[w+1], Asl[w+1]);
            split_pack(v1.x, v1.y, Ash[w+2], Asl[w+2]);
            split_pack(v1.z, v1.w, Ash[w+3], Asl[w+3]);
            split_pack(v2.x, v2.y, Ash[w+4], Asl[w+4]);
            split_pack(v2.z, v2.w, Ash[w+5], Asl[w+5]);
            split_pack(v3.x, v3.y, Ash[w+6], Asl[w+6]);
            split_pack(v3.z, v3.w, Ash[w+7], Asl[w+7]);
        }
        {
            const float* src = W + (size_t)(col0 + wr) * K + k0 + wk;
            float4 v0 = *(const float4*)(src);
            float4 v1 = *(const float4*)(src + 4);
            int w = wr * 20 + (wk >> 1);
            split_pack(v0.x, v0.y, Wsh[w+0], Wsl[w+0]);
            split_pack(v0.z, v0.w, Wsh[w+1], Wsl[w+1]);
            split_pack(v1.x, v1.y, Wsh[w+2], Wsl[w+2]);
            split_pack(v1.z, v1.w, Wsh[w+3], Wsl[w+3]);
        }
        __syncthreads();
        #pragma unroll
        for (int ks = 0; ks < 2; ks++) {
            uint32_t wbb = ks * 32;
            uint32_t ah[2][4], al[2][4], bh[4][2], bl[4][2];
            #pragma unroll
            for (int mi = 0; mi < 2; mi++) {
                ldsm4(ah[mi][0], ah[mi][1], ah[mi][2], ah[mi][3], aOffH[mi] + wbb);
                ldsm4(al[mi][0], al[mi][1], al[mi][2], al[mi][3], aOffL[mi] + wbb);
            }
            #pragma unroll
            for (int jj = 0; jj < 2; jj++) {
                ldsm4(bh[jj*2][0], bh[jj*2][1], bh[jj*2+1][0], bh[jj*2+1][1], bOffH[jj] + wbb);
                ldsm4(bl[jj*2][0], bl[jj*2][1], bl[jj*2+1][0], bl[jj*2+1][1], bOffL[jj] + wbb);
            }
            #pragma unroll
            for (int mi = 0; mi < 2; mi++)
                #pragma unroll
                for (int n = 0; n < 4; n++)
                    mma3(c[mi][n], ah[mi], al[mi], bh[n], bl[n]);
        }
    }
    #pragma unroll
    for (int mi = 0; mi < 2; mi++) {
        #pragma unroll
        for (int n = 0; n < 4; n++) {
            int col = col0 + wn * 32 + n * 8 + 2 * tig;
            float b0 = bias[col], b1 = bias[col + 1];
            int r0 = row0 + wq * 32 + mi * 16 + g;
            *(float2*)&C[(size_t)r0 * N + col] =
                make_float2(c[mi][n][0] + b0, c[mi][n][1] + b1);
            *(float2*)&C[(size_t)(r0 + 8) * N + col] =
                make_float2(c[mi][n][2] + b0, c[mi][n][3] + b1);
        }
    }
}

// ---------------- feature projection (unchanged, known-good) -----------------
__global__ __launch_bounds__(256) void featproj(
    const float* __restrict__ In, const float* __restrict__ P,
    uint32_t* __restrict__ Oh, uint32_t* __restrict__ Ol)
{
    __shared__ float Qsm[16][68];
    __shared__ float Psm[16][68];
    const int bh = blockIdx.z, b = bh >> 4, h = bh & 15;
    const int s0 = blockIdx.x * 64, f0 = blockIdx.y * 64;
    const int tid = threadIdx.x;
    const int ty = tid >> 4, tx = tid & 15;
    const int lr = tid >> 2;
    const int lk = (tid & 3) << 2;

    const float* qptr = In + ((size_t)(b * SEQ) + s0 + lr) * DMODEL + h * HD + lk;
    const float* pptr = P + (f0 + lr) * HD + lk;

    float c[4][4] = {};
    for (int k0 = 0; k0 < HD; k0 += 16) {
        float4 qv = *(const float4*)(qptr + k0);
        float4 pv = *(const float4*)(pptr + k0);
        Qsm[lk+0][lr] = qv.x; Qsm[lk+1][lr] = qv.y; Qsm[lk+2][lr] = qv.z; Qsm[lk+3][lr] = qv.w;
        Psm[lk+0][lr] = pv.x; Psm[lk+1][lr] = pv.y; Psm[lk+2][lr] = pv.z; Psm[lk+3][lr] = pv.w;
        __syncthreads();
        #pragma unroll
        for (int kk = 0; kk < 16; kk++) {
            float4 a4 = *(const float4*)&Qsm[kk][ty << 2];
            float4 b4 = *(const float4*)&Psm[kk][tx << 2];
            float a_[4] = {a4.x, a4.y, a4.z, a4.w};
            float b_[4] = {b4.x, b4.y, b4.z, b4.w};
            #pragma unroll
            for (int i = 0; i < 4; i++)
                #pragma unroll
                for (int j = 0; j < 4; j++)
                    c[i][j] += a_[i] * b_[j];
        }
        __syncthreads();
    }
    #pragma unroll
    for (int i = 0; i < 4; i++) {
        uint32_t h0, l0, h1, l1;
        split_pack(c[i][0], c[i][1], h0, l0);
        split_pack(c[i][2], c[i][3], h1, l1);
        size_t base = ((size_t)bh * SEQ + s0 + (ty << 2) + i) * (NF / 2)
                      + ((f0 + (tx << 2)) >> 1);
        *(uint2*)&Oh[base] = make_uint2(h0, h1);
        *(uint2*)&Ol[base] = make_uint2(l0, l1);
    }
}

// ---------------- flash attention: Q in regs, P in regs, 2 CTA/SM ------------
// CTA: 128 threads = 4 warps, each warp = 16q x 64t full-width rows.
// Smem: K hi/lo (64x132 words each) + V^T hi/lo (64x36 each) = 84KB.
#define QT 64
#define TT 64
#define KW 132        // K tile pitch (words): NF/2 + 4
#define VTW 36        // V^T pitch (words): TT/2 + 4

__global__ __launch_bounds__(128) void attn_bf3(
    const uint32_t* __restrict__ Qh, const uint32_t* __restrict__ Ql,
    const uint32_t* __restrict__ Kh, const uint32_t* __restrict__ Kl,
    const float* __restrict__ V, float* __restrict__ Ctx)
{
    extern __shared__ uint32_t smw[];
    uint32_t* Ksh = smw;                    // 64*132
    uint32_t* Ksl = Ksh + QT * KW;
    uint32_t* VtH = Ksl + QT * KW;          // 64*36
    uint32_t* VtL = VtH + 64 * VTW;

    const int tid  = threadIdx.x;
    const int lane = tid & 31, warp = tid >> 5;       // warp 0..3
    const int g = lane >> 2, tig = lane & 3;
    const int bh = blockIdx.y, b = bh >> 4, h = bh & 15;
    const int s0 = blockIdx.x * QT;
    const float scale = 0.0625f;   // 1/sqrt(256)

    // ldmatrix per-lane offsets
    const int arow = ((lane >> 3) & 1) * 8 + (lane & 7);
    const int acol = (lane >> 4) * 4;
    const int brow = (lane >> 4) * 8 + (lane & 7);
    const int bcol = ((lane >> 3) & 1) * 4;

    // ---- stage Q tile into K buffers, then load A-frags to registers ----
    for (int idx = tid; idx < QT * 32; idx += 128) {
        int r = idx >> 5, w4 = (idx & 31) << 2;
        size_t gb = ((size_t)bh * SEQ + s0 + r) * (NF / 2) + w4;
        *(uint4*)&Ksh[r * KW + w4] = *(const uint4*)&Qh[gb];
        *(uint4*)&Ksl[r * KW + w4] = *(const uint4*)&Ql[gb];
    }
    __syncthreads();
    uint32_t qfh[16][4], qfl[16][4];
    {
        uint32_t baseH = s2u(Ksh) + ((warp * 16 + arow) * KW + acol) * 4;
        uint32_t baseL = s2u(Ksl) + ((warp * 16 + arow) * KW + acol) * 4;
        #pragma unroll
        for (int ks = 0; ks < 16; ks++) {
            ldsm4(qfh[ks][0], qfh[ks][1], qfh[ks][2], qfh[ks][3], baseH + ks * 32);
            ldsm4(qfl[ks][0], qfl[ks][1], qfl[ks][2], qfl[ks][3], baseL + ks * 32);
        }
    }

    const uint32_t kBh = s2u(Ksh) + (brow * KW + bcol) * 4;
    const uint32_t kBl = s2u(Ksl) + (brow * KW + bcol) * 4;
    const uint32_t vBh = s2u(VtH) + (brow * VTW + bcol) * 4;
    const uint32_t vBl = s2u(VtL) + (brow * VTW + bcol) * 4;

    float o[8][4] = {};
    float m0 = -1e30f, m1 = -1e30f, l0 = 0.f, l1 = 0.f;

    for (int t0 = 0; t0 < SEQ; t0 += TT) {
        __syncthreads();   // previous iter's reads (and Q reg load) done
        // ---- fill K tile (hi+lo) ----
        for (int idx = tid; idx < TT * 32; idx += 128) {
            int r = idx >> 5, w4 = (idx & 31) << 2;
            size_t gb = ((size_t)bh * SEQ + t0 + r) * (NF / 2) + w4;
            *(uint4*)&Ksh[r * KW + w4] = *(const uint4*)&Kh[gb];
            *(uint4*)&Ksl[r * KW + w4] = *(const uint4*)&Kl[gb];
        }
        // ---- fill V^T pre-split: word (d, t/2) = bf16x2(v[t][d], v[t+1][d]) ----
        for (int idx = tid; idx < TT * 16; idx += 128) {
            int t = idx >> 4, d4 = (idx & 15) << 2;
            float4 v = *(const float4*)&V[((size_t)b * SEQ + t0 + t) * DMODEL + h * HD + d4];
            float4 p;
            p.x = __shfl_xor_sync(0xffffffffu, v.x, 16);
            p.y = __shfl_xor_sync(0xffffffffu, v.y, 16);
            p.z = __shfl_xor_sync(0xffffffffu, v.z, 16);
            p.w = __shfl_xor_sync(0xffffffffu, v.w, 16);
            float ve[4], vo[4];
            if (t & 1) {
                ve[0]=p.x; ve[1]=p.y; ve[2]=p.z; ve[3]=p.w;
                vo[0]=v.x; vo[1]=v.y; vo[2]=v.z; vo[3]=v.w;
            } else {
                ve[0]=v.x; ve[1]=v.y; ve[2]=v.z; ve[3]=v.w;
                vo[0]=p.x; vo[1]=p.y; vo[2]=p.z; vo[3]=p.w;
            }
            int i0 = (t & 1) ? 2 : 0;
            int tw = t >> 1;
            #pragma unroll
            for (int i = 0; i < 2; i++) {
                uint32_t hw, lw;
                split_pack(ve[i0 + i], vo[i0 + i], hw, lw);
                VtH[(d4 + i0 + i) * VTW + tw] = hw;
                VtL[(d4 + i0 + i) * VTW + tw] = lw;
            }
        }
        __syncthreads();

        // ---- scores: c[8][4] = Q(16q x 256f) @ K^T(256f x 64t) ----
        float c[8][4] = {};
        #pragma unroll
        for (int ks = 0; ks < 16; ks++) {
            uint32_t wbb = ks * 32;
            uint32_t bhf[8][2], blf[8][2];
            #pragma unroll
            for (int jj = 0; jj < 4; jj++) {
                uint32_t joff = jj * 16 * KW * 4 + wbb;
                ldsm4(bhf[jj*2][0], bhf[jj*2][1], bhf[jj*2+1][0], bhf[jj*2+1][1], kBh + joff);
                ldsm4(blf[jj*2][0], blf[jj*2][1], blf[jj*2+1][0], blf[jj*2+1][1], kBl + joff);
            }
            #pragma unroll
            for (int n = 0; n < 8; n++)
                mma3(c[n], qfh[ks], qfl[ks], bhf[n], blf[n]);
        }

        // ---- in-register softmax (rows g and g+8; reduce over tig lanes) ----
        float mx0 = -1e30f, mx1 = -1e30f;
        #pragma unroll
        for (int n = 0; n < 8; n++) {
            mx0 = fmaxf(mx0, fmaxf(c[n][0], c[n][1]));
            mx1 = fmaxf(mx1, fmaxf(c[n][2], c[n][3]));
        }
        mx0 = fmaxf(mx0, __shfl_xor_sync(0xffffffffu, mx0, 1));
        mx0 = fmaxf(mx0, __shfl_xor_sync(0xffffffffu, mx0, 2));
        mx1 = fmaxf(mx1, __shfl_xor_sync(0xffffffffu, mx1, 1));
        mx1 = fmaxf(mx1, __shfl_xor_sync(0xffffffffu, mx1, 2));
        float mn0 = fmaxf(m0, mx0 * scale), mn1 = fmaxf(m1, mx1 * scale);
        float a0 = __expf(m0 - mn0), a1 = __expf(m1 - mn1);
        float sum0 = 0.f, sum1 = 0.f;
        #pragma unroll
        for (int n = 0; n < 8; n++) {
            c[n][0] = __expf(fmaf(c[n][0], scale, -mn0));
            c[n][1] = __expf(fmaf(c[n][1], scale, -mn0));
            c[n][2] = __expf(fmaf(c[n][2], scale, -mn1));
            c[n][3] = __expf(fmaf(c[n][3], scale, -mn1));
            sum0 += c[n][0] + c[n][1];
            sum1 += c[n][2] + c[n][3];
        }
        sum0 += __shfl_xor_sync(0xffffffffu, sum0, 1);
        sum0 += __shfl_xor_sync(0xffffffffu, sum0, 2);
        sum1 += __shfl_xor_sync(0xffffffffu, sum1, 1);
        sum1 += __shfl_xor_sync(0xffffffffu, sum1, 2);
        l0 = l0 * a0 + sum0; m0 = mn0;
        l1 = l1 * a1 + sum1; m1 = mn1;

        // ---- P A-frags directly from exp'd C frags ----
        uint32_t pfh[4][4], pfl[4][4];
        #pragma unroll
        for (int k2 = 0; k2 < 4; k2++) {
            split_pack(c[2*k2  ][0], c[2*k2  ][1], pfh[k2][0], pfl[k2][0]);
            split_pack(c[2*k2  ][2], c[2*k2  ][3], pfh[k2][1], pfl[k2][1]);
            split_pack(c[2*k2+1][0], c[2*k2+1][1], pfh[k2][2], pfl[k2][2]);
            split_pack(c[2*k2+1][2], c[2*k2+1][3], pfh[k2][3], pfl[k2][3]);
        }

        // ---- rescale O, then O += P @ V ----
        #pragma unroll
        for (int n = 0; n < 8; n++) {
            o[n][0] *= a0; o[n][1] *= a0;
            o[n][2] *= a1; o[n][3] *= a1;
        }
        #pragma unroll
        for (int k2 = 0; k2 < 4; k2++) {
            uint32_t wbb = k2 * 32;
            uint32_t bhf[8][2], blf[8][2];
            #pragma unroll
            for (int jj = 0; jj < 4; jj++) {
                uint32_t joff = jj * 16 * VTW * 4 + wbb;
                ldsm4(bhf[jj*2][0], bhf[jj*2][1], bhf[jj*2+1][0], bhf[jj*2+1][1], vBh + joff);
                ldsm4(blf[jj*2][0], blf[jj*2][1], blf[jj*2+1][0], blf[jj*2+1][1], vBl + joff);
            }
            #pragma unroll
            for (int n = 0; n < 8; n++)
                mma3(o[n], pfh[k2], pfl[k2], bhf[n], blf[n]);
        }
    }

    // ---- epilogue ----
    float inv0 = 1.0f / l0, inv1 = 1.0f / l1;
    int r0 = s0 + warp * 16 + g;
    #pragma unroll
    for (int n = 0; n < 8; n++) {
        int dc = n * 8 + 2 * tig;
        *(float2*)&Ctx[((size_t)b * SEQ + r0) * DMODEL + h * HD + dc] =
            make_float2(o[n][0] * inv0, o[n][1] * inv0);
        *(float2*)&Ctx[((size_t)b * SEQ + r0 + 8) * DMODEL + h * HD + dc] =
            make_float2(o[n][2] * inv1, o[n][3] * inv1);
    }
}

// ---------------- launch ------------------------------------------------------
extern "C" void kernel_launch(void* const* d_in, const int* in_sizes, int n_in,
                              void* d_out, int out_size)
{
    (void)in_sizes; (void)n_in; (void)out_size;
    const float* x  = (const float*)d_in[0];
    const float* Wq = (const float*)d_in[1];
    const float* bq = (const float*)d_in[2];
    const float* Wk = (const float*)d_in[3];
    const float* bk = (const float*)d_in[4];
    const float* Wv = (const float*)d_in[5];
    const float* bv = (const float*)d_in[6];
    const float* Wo = (const float*)d_in[7];
    const float* bo = (const float*)d_in[8];
    const float* P  = (const float*)d_in[9];

    float *q, *k, *v, *ctx;
    uint32_t *qph, *qpl, *kph, *kpl;
    cudaGetSymbolAddress((void**)&q,   g_q);
    cudaGetSymbolAddress((void**)&k,   g_k);
    cudaGetSymbolAddress((void**)&v,   g_v);
    cudaGetSymbolAddress((void**)&ctx, g_ctx);
    cudaGetSymbolAddress((void**)&qph, g_qph);
    cudaGetSymbolAddress((void**)&qpl, g_qpl);
    cudaGetSymbolAddress((void**)&kph, g_kph);
    cudaGetSymbolAddress((void**)&kpl, g_kpl);

    dim3 gemm_grid(DMODEL / 64, MROWS / 128);   // (16, 64)
    gemm_bf3<<<gemm_grid, 256>>>(x, Wq, bq, q, DMODEL, DMODEL);
    gemm_bf3<<<gemm_grid, 256>>>(x, Wk, bk, k, DMODEL, DMODEL);
    gemm_bf3<<<gemm_grid, 256>>>(x, Wv, bv, v, DMODEL, DMODEL);

    dim3 fp_grid(SEQ / 64, NF / 64, BH);        // (32, 4, 128)
    featproj<<<fp_grid, 256>>>(q, P, qph, qpl);
    featproj<<<fp_grid, 256>>>(k, P, kph, kpl);

    const int ATT_SMEM = (QT * KW * 2 + 64 * VTW * 2) * 4;   // 86016 B -> 2 CTA/SM
    cudaFuncSetAttribute(attn_bf3, cudaFuncAttributeMaxDynamicSharedMemorySize, ATT_SMEM);
    attn_bf3<<<dim3(SEQ / QT, BH), 128, ATT_SMEM>>>(qph, qpl, kph, kpl, v, ctx);

    gemm_bf3<<<gemm_grid, 256>>>(ctx, Wo, bo, (float*)d_out, DMODEL, DMODEL);
}